// round 3
// baseline (speedup 1.0000x reference)
#include <cuda_runtime.h>

#define N_NODES 100000
#define N_EDGES 1600000
#define HDIM    64
#define NH      8
#define N_EMB   174   // sum of ATOM_DIMS
#define NFEAT   9
#define QK_SCALE 0.35355339059327373f  // 1/sqrt(8)

__constant__ int c_offs[NFEAT] = {0, 119, 124, 136, 148, 158, 164, 170, 172};

// ---------------- scratch (device globals; no allocations allowed) ----------
__device__ float g_embQ[N_EMB * HDIM];
__device__ float g_embK[N_EMB * HDIM];
__device__ float g_embV[N_EMB * HDIM];
__device__ float g_Q[N_NODES * HDIM];
__device__ float g_K[N_NODES * HDIM];
__device__ float g_V[N_NODES * HDIM];
__device__ float g_score[N_EDGES * NH];
__device__ float g_attn [N_EDGES * NH];
__device__ float g_mx  [N_NODES * NH];
__device__ float g_sinv[N_NODES * NH];
__device__ float g_AV[N_NODES * HDIM];
__device__ int   g_cnt   [N_NODES];
__device__ int   g_rowptr[N_NODES];
__device__ int   g_wcur  [N_NODES];
__device__ int2  g_sedge [N_EDGES];   // (orig edge id, col)

// ---------------- K0: zero histogram ----------------------------------------
__global__ void k_zero_cnt() {
    int i = blockIdx.x * blockDim.x + threadIdx.x;
    if (i < N_NODES) g_cnt[i] = 0;
}

// ---------------- K1a: embW = atom_emb @ W (fold scale into Q table) --------
__global__ void k_emb_gemm(const float* __restrict__ emb,
                           const float* __restrict__ Wq,
                           const float* __restrict__ Wk,
                           const float* __restrict__ Wv) {
    int r = blockIdx.x;                 // 0..173
    __shared__ float a[HDIM];
    int t = threadIdx.x;                // 192 threads: 3 mats x 64 cols
    if (t < HDIM) a[t] = emb[r * HDIM + t];
    __syncthreads();
    int mat = t >> 6, c = t & 63;
    const float* W = (mat == 0) ? Wq : (mat == 1) ? Wk : Wv;
    float acc = 0.f;
    #pragma unroll
    for (int j = 0; j < HDIM; j++) acc += a[j] * W[j * HDIM + c];
    if (mat == 0)      g_embQ[r * HDIM + c] = acc * QK_SCALE;
    else if (mat == 1) g_embK[r * HDIM + c] = acc;
    else               g_embV[r * HDIM + c] = acc;
}

// ---------------- K1b: per-node gather-sum -> Q,K,V -------------------------
__global__ void k_node_qkv(const int* __restrict__ X,
                           const float* __restrict__ bq,
                           const float* __restrict__ bk,
                           const float* __restrict__ bv) {
    int tid = blockIdx.x * blockDim.x + threadIdx.x;
    int n = tid >> 4;           // 16 threads/node, each does a float4 (4 cols)
    int t16 = tid & 15;
    if (n >= N_NODES) return;

    const float4* eq = (const float4*)g_embQ;
    const float4* ek = (const float4*)g_embK;
    const float4* ev = (const float4*)g_embV;

    float4 aq = ((const float4*)bq)[t16];
    aq.x *= QK_SCALE; aq.y *= QK_SCALE; aq.z *= QK_SCALE; aq.w *= QK_SCALE;
    float4 ak = ((const float4*)bk)[t16];
    float4 av = ((const float4*)bv)[t16];

    #pragma unroll
    for (int f = 0; f < NFEAT; f++) {
        int idx = X[n * NFEAT + f] + c_offs[f];
        int base = idx * 16 + t16;
        float4 q = eq[base]; aq.x += q.x; aq.y += q.y; aq.z += q.z; aq.w += q.w;
        float4 k = ek[base]; ak.x += k.x; ak.y += k.y; ak.z += k.z; ak.w += k.w;
        float4 v = ev[base]; av.x += v.x; av.y += v.y; av.z += v.z; av.w += v.w;
    }
    ((float4*)g_Q)[n * 16 + t16] = aq;
    ((float4*)g_K)[n * 16 + t16] = ak;
    ((float4*)g_V)[n * 16 + t16] = av;
}

// ---------------- K2: SDDMM (thread per edge) + histogram -------------------
__global__ void k_sddmm(const int* __restrict__ row, const int* __restrict__ col) {
    int e = blockIdx.x * blockDim.x + threadIdx.x;
    if (e >= N_EDGES) return;
    int r = row[e], c = col[e];
    const float4* q = (const float4*)(g_Q + r * HDIM);
    const float4* k = (const float4*)(g_K + c * HDIM);
    float s[8] = {0, 0, 0, 0, 0, 0, 0, 0};
    #pragma unroll
    for (int i = 0; i < 16; i++) {
        float4 a = q[i], b = k[i];
        int base = (i & 1) * 4;            // col = 4i+j, head = (4i+j)&7
        s[base + 0] += a.x * b.x;
        s[base + 1] += a.y * b.y;
        s[base + 2] += a.z * b.z;
        s[base + 3] += a.w * b.w;
    }
    float4* o = (float4*)(g_score + e * 8);
    o[0] = make_float4(s[0], s[1], s[2], s[3]);
    o[1] = make_float4(s[4], s[5], s[6], s[7]);
    atomicAdd(&g_cnt[r], 1);
}

// ---------------- K3: exclusive scan of counts (single block) ---------------
__global__ void k_scan() {
    __shared__ int sh[1024];
    __shared__ int s_carry;
    int t = threadIdx.x;
    if (t == 0) s_carry = 0;
    __syncthreads();
    for (int base = 0; base < N_NODES; base += 1024) {
        int idx = base + t;
        int v = (idx < N_NODES) ? g_cnt[idx] : 0;
        int x = v;
        sh[t] = x;
        __syncthreads();
        for (int o = 1; o < 1024; o <<= 1) {
            int y = (t >= o) ? sh[t - o] : 0;
            __syncthreads();
            x += y;
            sh[t] = x;
            __syncthreads();
        }
        int total = sh[1023];
        int carry = s_carry;
        if (idx < N_NODES) {
            int ex = carry + x - v;
            g_rowptr[idx] = ex;
            g_wcur[idx]   = ex;
        }
        __syncthreads();
        if (t == 0) s_carry = carry + total;
        __syncthreads();
    }
}

// ---------------- K4: scatter edges into CSR order --------------------------
__global__ void k_scatter(const int* __restrict__ row, const int* __restrict__ col) {
    int e = blockIdx.x * blockDim.x + threadIdx.x;
    if (e >= N_EDGES) return;
    int r = row[e];
    int pos = atomicAdd(&g_wcur[r], 1);
    g_sedge[pos] = make_int2(e, col[e]);
}

// ---------------- K5: per-row softmax stats (warp per node) -----------------
__global__ void k_softmax() {
    int g = blockIdx.x * blockDim.x + threadIdx.x;
    int n = g >> 5;
    if (n >= N_NODES) return;
    int lane = threadIdx.x & 31;
    int start = g_rowptr[n], len = g_cnt[n];
    int h = lane & 7, slot = lane >> 3;       // 4 edge slots x 8 heads

    float mx = -3.4e38f;
    for (int i = slot; i < len; i += 4) {
        int e = g_sedge[start + i].x;
        mx = fmaxf(mx, g_score[e * 8 + h]);
    }
    mx = fmaxf(mx, __shfl_xor_sync(0xffffffffu, mx, 8));
    mx = fmaxf(mx, __shfl_xor_sync(0xffffffffu, mx, 16));

    float sm = 0.f;
    for (int i = slot; i < len; i += 4) {
        int e = g_sedge[start + i].x;
        sm += __expf(g_score[e * 8 + h] - mx);
    }
    sm += __shfl_xor_sync(0xffffffffu, sm, 8);
    sm += __shfl_xor_sync(0xffffffffu, sm, 16);

    if (lane < 8) {
        g_mx[n * 8 + lane] = mx;
        g_sinv[n * 8 + lane] = (len > 0) ? (1.0f / sm) : 0.f;
    }
}

// ---------------- K6: normalized attention per edge -------------------------
__global__ void k_attn(const int* __restrict__ row) {
    int e = blockIdx.x * blockDim.x + threadIdx.x;
    if (e >= N_EDGES) return;
    int r = row[e];
    const float4* sp = (const float4*)(g_score + e * 8);
    float4 s0 = sp[0], s1 = sp[1];
    const float4* mp = (const float4*)(g_mx + r * 8);
    float4 m0 = mp[0], m1 = mp[1];
    const float4* ip = (const float4*)(g_sinv + r * 8);
    float4 i0 = ip[0], i1 = ip[1];
    float4 p0, p1;
    p0.x = __expf(s0.x - m0.x) * i0.x;
    p0.y = __expf(s0.y - m0.y) * i0.y;
    p0.z = __expf(s0.z - m0.z) * i0.z;
    p0.w = __expf(s0.w - m0.w) * i0.w;
    p1.x = __expf(s1.x - m1.x) * i1.x;
    p1.y = __expf(s1.y - m1.y) * i1.y;
    p1.z = __expf(s1.z - m1.z) * i1.z;
    p1.w = __expf(s1.w - m1.w) * i1.w;
    float4* ap = (float4*)(g_attn + e * 8);
    ap[0] = p0; ap[1] = p1;
}

// ---------------- K7: SpMM (warp per node, register accumulators) -----------
__global__ void k_spmm() {
    int g = blockIdx.x * blockDim.x + threadIdx.x;
    int n = g >> 5;
    if (n >= N_NODES) return;
    int lane = threadIdx.x & 31;
    int start = g_rowptr[n], len = g_cnt[n];
    int c0 = 2 * lane;
    int h0 = c0 & 7, h1 = (c0 + 1) & 7;
    float2 acc = make_float2(0.f, 0.f);
    for (int i = 0; i < len; i++) {
        int2 ec = g_sedge[start + i];
        float p0 = g_attn[ec.x * 8 + h0];
        float p1 = g_attn[ec.x * 8 + h1];
        float2 v = *(const float2*)(g_V + ec.y * HDIM + c0);
        acc.x += p0 * v.x;
        acc.y += p1 * v.y;
    }
    *(float2*)(g_AV + n * HDIM + c0) = acc;
}

// ---------------- K8: out = AV @ Wo + bo (Wo register-resident) -------------
__global__ __launch_bounds__(128) void k_out(const float* __restrict__ Wo,
                                             const float* __restrict__ bo,
                                             float* __restrict__ out) {
    int lane = threadIdx.x & 31;
    int wglobal = (blockIdx.x * blockDim.x + threadIdx.x) >> 5;
    int nwarps = (gridDim.x * blockDim.x) >> 5;

    float2 w[64];
    #pragma unroll
    for (int j = 0; j < 64; j++)
        w[j] = *(const float2*)(Wo + j * HDIM + 2 * lane);
    float2 b = *(const float2*)(bo + 2 * lane);

    for (int n = wglobal; n < N_NODES; n += nwarps) {
        float2 a = *(const float2*)(g_AV + n * HDIM + 2 * lane);
        float ax = a.x, ay = a.y;
        float2 acc = b;
        #pragma unroll
        for (int l = 0; l < 32; l++) {
            float x = __shfl_sync(0xffffffffu, ax, l);  // a[2l]
            float y = __shfl_sync(0xffffffffu, ay, l);  // a[2l+1]
            acc.x += x * w[2 * l].x + y * w[2 * l + 1].x;
            acc.y += x * w[2 * l].y + y * w[2 * l + 1].y;
        }
        *(float2*)(out + n * HDIM + 2 * lane) = acc;
    }
}

// ---------------- launch -----------------------------------------------------
extern "C" void kernel_launch(void* const* d_in, const int* in_sizes, int n_in,
                              void* d_out, int out_size) {
    const int*   X        = (const int*)  d_in[0];
    const int*   row      = (const int*)  d_in[1];
    const int*   col      = (const int*)  d_in[2];
    const float* atom_emb = (const float*)d_in[3];
    const float* Wq       = (const float*)d_in[4];
    const float* bq       = (const float*)d_in[5];
    const float* Wk       = (const float*)d_in[6];
    const float* bk       = (const float*)d_in[7];
    const float* Wv       = (const float*)d_in[8];
    const float* bv       = (const float*)d_in[9];
    const float* Wo       = (const float*)d_in[10];
    const float* bo       = (const float*)d_in[11];
    float* out = (float*)d_out;

    (void)in_sizes; (void)n_in; (void)out_size;

    k_zero_cnt<<<(N_NODES + 255) / 256, 256>>>();
    k_emb_gemm<<<N_EMB, 192>>>(atom_emb, Wq, Wk, Wv);
    k_node_qkv<<<(N_NODES * 16 + 255) / 256, 256>>>(X, bq, bk, bv);
    k_sddmm<<<(N_EDGES + 255) / 256, 256>>>(row, col);
    k_scan<<<1, 1024>>>();
    k_scatter<<<(N_EDGES + 255) / 256, 256>>>(row, col);
    k_softmax<<<(N_NODES * 32 + 255) / 256, 256>>>();
    k_attn<<<(N_EDGES + 255) / 256, 256>>>(row);
    k_spmm<<<(N_NODES * 32 + 255) / 256, 256>>>();
    k_out<<<592, 128>>>(Wo, bo, out);
}

// round 4
// speedup vs baseline: 1.1137x; 1.1137x over previous
#include <cuda_runtime.h>

#define N_NODES 100000
#define N_EDGES 1600000
#define HDIM    64
#define NH      8
#define N_EMB   174   // sum of ATOM_DIMS
#define NFEAT   9
#define QK_SCALE 0.35355339059327373f  // 1/sqrt(8)

__constant__ int c_offs[NFEAT] = {0, 119, 124, 136, 148, 158, 164, 170, 172};

// ---------------- scratch (device globals; no allocations allowed) ----------
__device__ float g_embQ[N_EMB * HDIM];
__device__ float g_embK[N_EMB * HDIM];
__device__ float g_embV[N_EMB * HDIM];
__device__ float g_Q[N_NODES * HDIM];
__device__ float g_K[N_NODES * HDIM];
__device__ float g_V[N_NODES * HDIM];
__device__ float g_score[(size_t)N_EDGES * NH];   // CSR-ordered scores
__device__ float g_AV[N_NODES * HDIM];
__device__ int   g_cnt   [N_NODES];
__device__ int   g_rowptr[N_NODES];
__device__ int   g_wcur  [N_NODES];
__device__ int   g_scol  [N_EDGES];               // CSR-ordered col indices

// ---------------- K0: zero histogram ----------------------------------------
__global__ void k_zero_cnt() {
    int i = blockIdx.x * blockDim.x + threadIdx.x;
    if (i < N_NODES) g_cnt[i] = 0;
}

// ---------------- K1a: embW = atom_emb @ W (fold scale into Q table) --------
__global__ void k_emb_gemm(const float* __restrict__ emb,
                           const float* __restrict__ Wq,
                           const float* __restrict__ Wk,
                           const float* __restrict__ Wv) {
    int r = blockIdx.x;                 // 0..173
    __shared__ float a[HDIM];
    int t = threadIdx.x;                // 192 threads: 3 mats x 64 cols
    if (t < HDIM) a[t] = emb[r * HDIM + t];
    __syncthreads();
    int mat = t >> 6, c = t & 63;
    const float* W = (mat == 0) ? Wq : (mat == 1) ? Wk : Wv;
    float acc = 0.f;
    #pragma unroll
    for (int j = 0; j < HDIM; j++) acc += a[j] * W[j * HDIM + c];
    if (mat == 0)      g_embQ[r * HDIM + c] = acc * QK_SCALE;
    else if (mat == 1) g_embK[r * HDIM + c] = acc;
    else               g_embV[r * HDIM + c] = acc;
}

// ---------------- K1b: per-node gather-sum -> Q,K,V -------------------------
__global__ void k_node_qkv(const int* __restrict__ X,
                           const float* __restrict__ bq,
                           const float* __restrict__ bk,
                           const float* __restrict__ bv) {
    int tid = blockIdx.x * blockDim.x + threadIdx.x;
    int n = tid >> 4;           // 16 threads/node, each does a float4 (4 cols)
    int t16 = tid & 15;
    if (n >= N_NODES) return;

    const float4* eq = (const float4*)g_embQ;
    const float4* ek = (const float4*)g_embK;
    const float4* ev = (const float4*)g_embV;

    float4 aq = ((const float4*)bq)[t16];
    aq.x *= QK_SCALE; aq.y *= QK_SCALE; aq.z *= QK_SCALE; aq.w *= QK_SCALE;
    float4 ak = ((const float4*)bk)[t16];
    float4 av = ((const float4*)bv)[t16];

    #pragma unroll
    for (int f = 0; f < NFEAT; f++) {
        int idx = X[n * NFEAT + f] + c_offs[f];
        int base = idx * 16 + t16;
        float4 q = eq[base]; aq.x += q.x; aq.y += q.y; aq.z += q.z; aq.w += q.w;
        float4 k = ek[base]; ak.x += k.x; ak.y += k.y; ak.z += k.z; ak.w += k.w;
        float4 v = ev[base]; av.x += v.x; av.y += v.y; av.z += v.z; av.w += v.w;
    }
    ((float4*)g_Q)[n * 16 + t16] = aq;
    ((float4*)g_K)[n * 16 + t16] = ak;
    ((float4*)g_V)[n * 16 + t16] = av;
}

// ---------------- K2: histogram of destination rows -------------------------
__global__ void k_hist(const int* __restrict__ row) {
    int e = blockIdx.x * blockDim.x + threadIdx.x;
    if (e < N_EDGES) atomicAdd(&g_cnt[row[e]], 1);
}

// ---------------- K3: exclusive scan (single block, warp-shuffle based) -----
__global__ __launch_bounds__(1024) void k_scan() {
    __shared__ int wsum[32];
    const int PER = 98;                 // 1024*98 = 100352 >= N_NODES
    int t = threadIdx.x;
    int lane = t & 31, wid = t >> 5;
    int base = t * PER;

    int local = 0;
    for (int j = 0; j < PER; j++) {
        int idx = base + j;
        if (idx < N_NODES) local += g_cnt[idx];
    }
    int v = local;
    #pragma unroll
    for (int o = 1; o < 32; o <<= 1) {
        int y = __shfl_up_sync(0xffffffffu, v, o);
        if (lane >= o) v += y;
    }
    if (lane == 31) wsum[wid] = v;
    __syncthreads();
    if (wid == 0) {
        int w = wsum[lane];
        #pragma unroll
        for (int o = 1; o < 32; o <<= 1) {
            int y = __shfl_up_sync(0xffffffffu, w, o);
            if (lane >= o) w += y;
        }
        wsum[lane] = w;
    }
    __syncthreads();
    int run = v - local + (wid > 0 ? wsum[wid - 1] : 0);
    for (int j = 0; j < PER; j++) {
        int idx = base + j;
        if (idx < N_NODES) {
            g_rowptr[idx] = run;
            g_wcur[idx]   = run;
            run += g_cnt[idx];
        }
    }
}

// ---------------- K4: scatter col indices into CSR order --------------------
__global__ void k_scatter(const int* __restrict__ row, const int* __restrict__ col) {
    int e = blockIdx.x * blockDim.x + threadIdx.x;
    if (e >= N_EDGES) return;
    int r = row[e];
    int pos = atomicAdd(&g_wcur[r], 1);
    g_scol[pos] = col[e];
}

// ---------------- K5: fused SDDMM + softmax + SpMM (warp per node) ----------
// lane holds columns c0=2*lane, c0+1 of Q (regs), K, V rows.
// head of col c is c&7, so lane's heads are h0=c0&7 and h0+1.
// Cross-lane dot reduction over d: lanes {ln, ln^4, ln^8, ln^16} share head.
__global__ __launch_bounds__(256) void k_fused() {
    int g = blockIdx.x * blockDim.x + threadIdx.x;
    int n = g >> 5;
    if (n >= N_NODES) return;
    int lane = threadIdx.x & 31;
    int start = g_rowptr[n], len = g_cnt[n];
    int c0 = 2 * lane, h0 = c0 & 7;

    float2 q = *(const float2*)(g_Q + n * HDIM + c0);

    // ---- pass 1: scores (stored CSR-order) + per-head running max ----
    float mx0 = -3.4e38f, mx1 = -3.4e38f;
    #pragma unroll 2
    for (int i = 0; i < len; i++) {
        int c = g_scol[start + i];
        float2 k = *(const float2*)(g_K + c * HDIM + c0);
        float s0 = q.x * k.x;
        float s1 = q.y * k.y;
        s0 += __shfl_xor_sync(0xffffffffu, s0, 4);
        s1 += __shfl_xor_sync(0xffffffffu, s1, 4);
        s0 += __shfl_xor_sync(0xffffffffu, s0, 8);
        s1 += __shfl_xor_sync(0xffffffffu, s1, 8);
        s0 += __shfl_xor_sync(0xffffffffu, s0, 16);
        s1 += __shfl_xor_sync(0xffffffffu, s1, 16);
        // lanes 0..3 now hold heads 0..7 pairwise (c0 = 0,2,4,6)
        if (lane < 4)
            *(float2*)(g_score + (size_t)(start + i) * 8 + c0) = make_float2(s0, s1);
        mx0 = fmaxf(mx0, s0);
        mx1 = fmaxf(mx1, s1);
    }

    // ---- pass 2: exp-normalize + V accumulate ----
    float sum0 = 0.f, sum1 = 0.f;
    float2 acc = make_float2(0.f, 0.f);
    #pragma unroll 2
    for (int i = 0; i < len; i++) {
        int c = g_scol[start + i];
        float2 sc = *(const float2*)(g_score + (size_t)(start + i) * 8 + h0);
        float p0 = __expf(sc.x - mx0);
        float p1 = __expf(sc.y - mx1);
        sum0 += p0; sum1 += p1;
        float2 v = *(const float2*)(g_V + c * HDIM + c0);
        acc.x += p0 * v.x;
        acc.y += p1 * v.y;
    }
    if (len > 0) {
        acc.x *= (1.0f / sum0);
        acc.y *= (1.0f / sum1);
    }
    *(float2*)(g_AV + n * HDIM + c0) = acc;
}

// ---------------- K6: out = AV @ Wo + bo (Wo register-resident) -------------
__global__ __launch_bounds__(128) void k_out(const float* __restrict__ Wo,
                                             const float* __restrict__ bo,
                                             float* __restrict__ out) {
    int lane = threadIdx.x & 31;
    int wglobal = (blockIdx.x * blockDim.x + threadIdx.x) >> 5;
    int nwarps = (gridDim.x * blockDim.x) >> 5;

    float2 w[64];
    #pragma unroll
    for (int j = 0; j < 64; j++)
        w[j] = *(const float2*)(Wo + j * HDIM + 2 * lane);
    float2 b = *(const float2*)(bo + 2 * lane);

    for (int n = wglobal; n < N_NODES; n += nwarps) {
        float2 a = *(const float2*)(g_AV + n * HDIM + 2 * lane);
        float ax = a.x, ay = a.y;
        float2 acc = b;
        #pragma unroll
        for (int l = 0; l < 32; l++) {
            float x = __shfl_sync(0xffffffffu, ax, l);  // a[2l]
            float y = __shfl_sync(0xffffffffu, ay, l);  // a[2l+1]
            acc.x += x * w[2 * l].x + y * w[2 * l + 1].x;
            acc.y += x * w[2 * l].y + y * w[2 * l + 1].y;
        }
        *(float2*)(out + n * HDIM + 2 * lane) = acc;
    }
}

// ---------------- launch -----------------------------------------------------
extern "C" void kernel_launch(void* const* d_in, const int* in_sizes, int n_in,
                              void* d_out, int out_size) {
    const int*   X        = (const int*)  d_in[0];
    const int*   row      = (const int*)  d_in[1];
    const int*   col      = (const int*)  d_in[2];
    const float* atom_emb = (const float*)d_in[3];
    const float* Wq       = (const float*)d_in[4];
    const float* bq       = (const float*)d_in[5];
    const float* Wk       = (const float*)d_in[6];
    const float* bk       = (const float*)d_in[7];
    const float* Wv       = (const float*)d_in[8];
    const float* bv       = (const float*)d_in[9];
    const float* Wo       = (const float*)d_in[10];
    const float* bo       = (const float*)d_in[11];
    float* out = (float*)d_out;

    (void)in_sizes; (void)n_in; (void)out_size;

    k_zero_cnt<<<(N_NODES + 255) / 256, 256>>>();
    k_emb_gemm<<<N_EMB, 192>>>(atom_emb, Wq, Wk, Wv);
    k_node_qkv<<<(N_NODES * 16 + 255) / 256, 256>>>(X, bq, bk, bv);
    k_hist<<<(N_EDGES + 255) / 256, 256>>>(row);
    k_scan<<<1, 1024>>>();
    k_scatter<<<(N_EDGES + 255) / 256, 256>>>(row, col);
    k_fused<<<(N_NODES * 32 + 255) / 256, 256>>>();
    k_out<<<1184, 128>>>(Wo, bo, out);
}

// round 6
// speedup vs baseline: 2.1801x; 1.9576x over previous
#include <cuda_runtime.h>

#define N_NODES 100000
#define N_EDGES 1600000
#define HDIM    64
#define NH      8
#define N_EMB   174   // sum of ATOM_DIMS
#define NFEAT   9
#define QK_SCALE 0.35355339059327373f  // 1/sqrt(8)

#define SCAN_NB   200
#define SCAN_BS   512   // 200*512 = 102400 >= N_NODES

__constant__ int c_offs[NFEAT] = {0, 119, 124, 136, 148, 158, 164, 170, 172};

// ---------------- scratch (device globals; no allocations allowed) ----------
__device__ float g_embQ[N_EMB * HDIM];
__device__ float g_embK[N_EMB * HDIM];
__device__ float g_embV[N_EMB * HDIM];
__device__ float g_Q[N_NODES * HDIM];
__device__ float g_K[N_NODES * HDIM];
__device__ float g_V[N_NODES * HDIM];
__device__ float g_score[(size_t)N_EDGES * NH];   // CSR-ordered scores
__device__ float g_AV[N_NODES * HDIM];
__device__ int   g_cnt   [N_NODES];
__device__ int   g_rowptr[N_NODES];
__device__ int   g_wcur  [N_NODES];
__device__ int   g_scol  [N_EDGES];               // CSR-ordered col indices
__device__ int   g_bsum  [SCAN_NB];
__device__ int   g_boff  [SCAN_NB];

// ---------------- K0: zero histogram ----------------------------------------
__global__ void k_zero_cnt() {
    int i = blockIdx.x * blockDim.x + threadIdx.x;
    if (i < N_NODES) g_cnt[i] = 0;
}

// ---------------- K1a: embW = atom_emb @ W (fold scale into Q table) --------
__global__ void k_emb_gemm(const float* __restrict__ emb,
                           const float* __restrict__ Wq,
                           const float* __restrict__ Wk,
                           const float* __restrict__ Wv) {
    int r = blockIdx.x;                 // 0..173
    __shared__ float a[HDIM];
    int t = threadIdx.x;                // 192 threads: 3 mats x 64 cols
    if (t < HDIM) a[t] = emb[r * HDIM + t];
    __syncthreads();
    int mat = t >> 6, c = t & 63;
    const float* W = (mat == 0) ? Wq : (mat == 1) ? Wk : Wv;
    float acc = 0.f;
    #pragma unroll
    for (int j = 0; j < HDIM; j++) acc += a[j] * W[j * HDIM + c];
    if (mat == 0)      g_embQ[r * HDIM + c] = acc * QK_SCALE;
    else if (mat == 1) g_embK[r * HDIM + c] = acc;
    else               g_embV[r * HDIM + c] = acc;
}

// ---------------- K1b: per-node gather-sum -> Q,K,V -------------------------
__global__ void k_node_qkv(const int* __restrict__ X,
                           const float* __restrict__ bq,
                           const float* __restrict__ bk,
                           const float* __restrict__ bv) {
    int tid = blockIdx.x * blockDim.x + threadIdx.x;
    int n = tid >> 4;           // 16 threads/node, each does a float4 (4 cols)
    int t16 = tid & 15;
    if (n >= N_NODES) return;

    const float4* eq = (const float4*)g_embQ;
    const float4* ek = (const float4*)g_embK;
    const float4* ev = (const float4*)g_embV;

    float4 aq = ((const float4*)bq)[t16];
    aq.x *= QK_SCALE; aq.y *= QK_SCALE; aq.z *= QK_SCALE; aq.w *= QK_SCALE;
    float4 ak = ((const float4*)bk)[t16];
    float4 av = ((const float4*)bv)[t16];

    #pragma unroll
    for (int f = 0; f < NFEAT; f++) {
        int idx = X[n * NFEAT + f] + c_offs[f];
        int base = idx * 16 + t16;
        float4 q = eq[base]; aq.x += q.x; aq.y += q.y; aq.z += q.z; aq.w += q.w;
        float4 k = ek[base]; ak.x += k.x; ak.y += k.y; ak.z += k.z; ak.w += k.w;
        float4 v = ev[base]; av.x += v.x; av.y += v.y; av.z += v.z; av.w += v.w;
    }
    ((float4*)g_Q)[n * 16 + t16] = aq;
    ((float4*)g_K)[n * 16 + t16] = ak;
    ((float4*)g_V)[n * 16 + t16] = av;
}

// ---------------- K2: histogram of destination rows -------------------------
__global__ void k_hist(const int* __restrict__ row) {
    int e = blockIdx.x * blockDim.x + threadIdx.x;
    if (e < N_EDGES) atomicAdd(&g_cnt[row[e]], 1);
}

// ---------------- K3a: per-block sums (coalesced) ----------------------------
__global__ __launch_bounds__(SCAN_BS) void k_scan1() {
    __shared__ int ws[SCAN_BS / 32];
    int t = threadIdx.x, b = blockIdx.x;
    int idx = b * SCAN_BS + t;
    int v = (idx < N_NODES) ? g_cnt[idx] : 0;
    int s = v;
    #pragma unroll
    for (int o = 1; o < 32; o <<= 1) s += __shfl_xor_sync(0xffffffffu, s, o);
    if ((t & 31) == 0) ws[t >> 5] = s;
    __syncthreads();
    if (t == 0) {
        int tot = 0;
        #pragma unroll
        for (int i = 0; i < SCAN_BS / 32; i++) tot += ws[i];
        g_bsum[b] = tot;
    }
}

// ---------------- K3b: exclusive scan of 200 block sums ----------------------
__global__ __launch_bounds__(256) void k_scan2() {
    __shared__ int ws[8];
    int t = threadIdx.x;
    int lane = t & 31, wid = t >> 5;
    int v = (t < SCAN_NB) ? g_bsum[t] : 0;
    int inc = v;
    #pragma unroll
    for (int o = 1; o < 32; o <<= 1) {
        int y = __shfl_up_sync(0xffffffffu, inc, o);
        if (lane >= o) inc += y;
    }
    if (lane == 31) ws[wid] = inc;
    __syncthreads();
    if (wid == 0) {                       // ALL 32 lanes execute the shuffles
        int x = (lane < 8) ? ws[lane] : 0;
        #pragma unroll
        for (int o = 1; o < 8; o <<= 1) {
            int y = __shfl_up_sync(0xffffffffu, x, o);
            if (lane >= o) x += y;
        }
        if (lane < 8) ws[lane] = x;
    }
    __syncthreads();
    int off = (wid > 0) ? ws[wid - 1] : 0;
    if (t < SCAN_NB) g_boff[t] = off + inc - v;   // exclusive
}

// ---------------- K3c: block exclusive scan + global offset -----------------
__global__ __launch_bounds__(SCAN_BS) void k_scan3() {
    __shared__ int ws[SCAN_BS / 32];
    int t = threadIdx.x, b = blockIdx.x;
    int lane = t & 31, wid = t >> 5;
    int idx = b * SCAN_BS + t;
    int v = (idx < N_NODES) ? g_cnt[idx] : 0;
    int inc = v;
    #pragma unroll
    for (int o = 1; o < 32; o <<= 1) {
        int y = __shfl_up_sync(0xffffffffu, inc, o);
        if (lane >= o) inc += y;
    }
    if (lane == 31) ws[wid] = inc;
    __syncthreads();
    if (wid == 0) {                       // ALL 32 lanes execute the shuffles
        int x = (lane < SCAN_BS / 32) ? ws[lane] : 0;
        #pragma unroll
        for (int o = 1; o < SCAN_BS / 32; o <<= 1) {
            int y = __shfl_up_sync(0xffffffffu, x, o);
            if (lane >= o) x += y;
        }
        if (lane < SCAN_BS / 32) ws[lane] = x;
    }
    __syncthreads();
    int off = g_boff[b] + ((wid > 0) ? ws[wid - 1] : 0);
    if (idx < N_NODES) {
        int ex = off + inc - v;
        g_rowptr[idx] = ex;
        g_wcur[idx]   = ex;
    }
}

// ---------------- K4: scatter col indices into CSR order --------------------
__global__ void k_scatter(const int* __restrict__ row, const int* __restrict__ col) {
    int e = blockIdx.x * blockDim.x + threadIdx.x;
    if (e >= N_EDGES) return;
    int r = row[e];
    int pos = atomicAdd(&g_wcur[r], 1);
    g_scol[pos] = col[e];
}

// ---------------- K5: fused SDDMM + softmax + SpMM (warp per node) ----------
__global__ __launch_bounds__(256) void k_fused() {
    int g = blockIdx.x * blockDim.x + threadIdx.x;
    int n = g >> 5;
    if (n >= N_NODES) return;
    int lane = threadIdx.x & 31;
    int start = g_rowptr[n], len = g_cnt[n];
    int c0 = 2 * lane, h0 = c0 & 7;

    float2 q = *(const float2*)(g_Q + n * HDIM + c0);

    // ---- pass 1: scores (stored CSR-order) + per-head running max ----
    float mx0 = -3.4e38f, mx1 = -3.4e38f;
    #pragma unroll 4
    for (int i = 0; i < len; i++) {
        int c = g_scol[start + i];
        float2 k = *(const float2*)(g_K + c * HDIM + c0);
        float s0 = q.x * k.x;
        float s1 = q.y * k.y;
        s0 += __shfl_xor_sync(0xffffffffu, s0, 4);
        s1 += __shfl_xor_sync(0xffffffffu, s1, 4);
        s0 += __shfl_xor_sync(0xffffffffu, s0, 8);
        s1 += __shfl_xor_sync(0xffffffffu, s1, 8);
        s0 += __shfl_xor_sync(0xffffffffu, s0, 16);
        s1 += __shfl_xor_sync(0xffffffffu, s1, 16);
        if (lane < 4)
            *(float2*)(g_score + (size_t)(start + i) * 8 + c0) = make_float2(s0, s1);
        mx0 = fmaxf(mx0, s0);
        mx1 = fmaxf(mx1, s1);
    }

    // ---- pass 2: exp-normalize + V accumulate ----
    float sum0 = 0.f, sum1 = 0.f;
    float2 acc = make_float2(0.f, 0.f);
    #pragma unroll 4
    for (int i = 0; i < len; i++) {
        int c = g_scol[start + i];
        float2 sc = *(const float2*)(g_score + (size_t)(start + i) * 8 + h0);
        float p0 = __expf(sc.x - mx0);
        float p1 = __expf(sc.y - mx1);
        sum0 += p0; sum1 += p1;
        float2 v = *(const float2*)(g_V + c * HDIM + c0);
        acc.x += p0 * v.x;
        acc.y += p1 * v.y;
    }
    if (len > 0) {
        acc.x *= (1.0f / sum0);
        acc.y *= (1.0f / sum1);
    }
    *(float2*)(g_AV + n * HDIM + c0) = acc;
}

// ---------------- K6: out = AV @ Wo + bo (Wo register-resident) -------------
__global__ __launch_bounds__(128) void k_out(const float* __restrict__ Wo,
                                             const float* __restrict__ bo,
                                             float* __restrict__ out) {
    int lane = threadIdx.x & 31;
    int wglobal = (blockIdx.x * blockDim.x + threadIdx.x) >> 5;
    int nwarps = (gridDim.x * blockDim.x) >> 5;

    float2 w[64];
    #pragma unroll
    for (int j = 0; j < 64; j++)
        w[j] = *(const float2*)(Wo + j * HDIM + 2 * lane);
    float2 b = *(const float2*)(bo + 2 * lane);

    for (int n = wglobal; n < N_NODES; n += nwarps) {
        float2 a = *(const float2*)(g_AV + n * HDIM + 2 * lane);
        float ax = a.x, ay = a.y;
        float2 acc = b;
        #pragma unroll
        for (int l = 0; l < 32; l++) {
            float x = __shfl_sync(0xffffffffu, ax, l);  // a[2l]
            float y = __shfl_sync(0xffffffffu, ay, l);  // a[2l+1]
            acc.x += x * w[2 * l].x + y * w[2 * l + 1].x;
            acc.y += x * w[2 * l].y + y * w[2 * l + 1].y;
        }
        *(float2*)(out + n * HDIM + 2 * lane) = acc;
    }
}

// ---------------- launch -----------------------------------------------------
extern "C" void kernel_launch(void* const* d_in, const int* in_sizes, int n_in,
                              void* d_out, int out_size) {
    const int*   X        = (const int*)  d_in[0];
    const int*   row      = (const int*)  d_in[1];
    const int*   col      = (const int*)  d_in[2];
    const float* atom_emb = (const float*)d_in[3];
    const float* Wq       = (const float*)d_in[4];
    const float* bq       = (const float*)d_in[5];
    const float* Wk       = (const float*)d_in[6];
    const float* bk       = (const float*)d_in[7];
    const float* Wv       = (const float*)d_in[8];
    const float* bv       = (const float*)d_in[9];
    const float* Wo       = (const float*)d_in[10];
    const float* bo       = (const float*)d_in[11];
    float* out = (float*)d_out;

    (void)in_sizes; (void)n_in; (void)out_size;

    k_zero_cnt<<<(N_NODES + 255) / 256, 256>>>();
    k_emb_gemm<<<N_EMB, 192>>>(atom_emb, Wq, Wk, Wv);
    k_node_qkv<<<(N_NODES * 16 + 255) / 256, 256>>>(X, bq, bk, bv);
    k_hist<<<(N_EDGES + 255) / 256, 256>>>(row);
    k_scan1<<<SCAN_NB, SCAN_BS>>>();
    k_scan2<<<1, 256>>>();
    k_scan3<<<SCAN_NB, SCAN_BS>>>();
    k_scatter<<<(N_EDGES + 255) / 256, 256>>>(row, col);
    k_fused<<<(N_NODES * 32 + 255) / 256, 256>>>();
    k_out<<<1184, 128>>>(Wo, bo, out);
}

// round 7
// speedup vs baseline: 2.8882x; 1.3248x over previous
#include <cuda_runtime.h>
#include <cuda_fp16.h>

#define N_NODES 100000
#define N_EDGES 1600000
#define HDIM    64
#define NH      8
#define N_EMB   174   // sum of ATOM_DIMS
#define NFEAT   9
#define QK_SCALE 0.35355339059327373f  // 1/sqrt(8)

#define SCAN_NB   200
#define SCAN_BS   512   // 200*512 = 102400 >= N_NODES

__constant__ int c_offs[NFEAT] = {0, 119, 124, 136, 148, 158, 164, 170, 172};

// ---------------- scratch (device globals; no allocations allowed) ----------
__device__ float  g_embQ[N_EMB * HDIM];
__device__ float  g_embK[N_EMB * HDIM];
__device__ float  g_embV[N_EMB * HDIM];
__device__ float  g_Q[N_NODES * HDIM];
__device__ float  g_K[N_NODES * HDIM];
__device__ __half g_Vh[N_NODES * HDIM];
__device__ float  g_AV[N_NODES * HDIM];
__device__ int    g_cnt   [N_NODES];
__device__ int    g_rowptr[N_NODES];
__device__ int    g_wcur  [N_NODES];
__device__ int    g_scol  [N_EDGES];              // CSR-ordered col indices
__device__ int    g_bsum  [SCAN_NB];
__device__ int    g_boff  [SCAN_NB];

// ---------------- K0: zero histogram ----------------------------------------
__global__ void k_zero_cnt() {
    int i = blockIdx.x * blockDim.x + threadIdx.x;
    if (i < N_NODES) g_cnt[i] = 0;
}

// ---------------- K1a: embW = atom_emb @ W (fold scale into Q table) --------
__global__ void k_emb_gemm(const float* __restrict__ emb,
                           const float* __restrict__ Wq,
                           const float* __restrict__ Wk,
                           const float* __restrict__ Wv) {
    int r = blockIdx.x;                 // 0..173
    __shared__ float a[HDIM];
    int t = threadIdx.x;                // 192 threads: 3 mats x 64 cols
    if (t < HDIM) a[t] = emb[r * HDIM + t];
    __syncthreads();
    int mat = t >> 6, c = t & 63;
    const float* W = (mat == 0) ? Wq : (mat == 1) ? Wk : Wv;
    float acc = 0.f;
    #pragma unroll
    for (int j = 0; j < HDIM; j++) acc += a[j] * W[j * HDIM + c];
    if (mat == 0)      g_embQ[r * HDIM + c] = acc * QK_SCALE;
    else if (mat == 1) g_embK[r * HDIM + c] = acc;
    else               g_embV[r * HDIM + c] = acc;
}

// ---------------- K1b: per-node gather-sum -> Q,K,V (V stored fp16) ---------
__global__ void k_node_qkv(const int* __restrict__ X,
                           const float* __restrict__ bq,
                           const float* __restrict__ bk,
                           const float* __restrict__ bv) {
    int tid = blockIdx.x * blockDim.x + threadIdx.x;
    int n = tid >> 4;           // 16 threads/node, each does a float4 (4 cols)
    int t16 = tid & 15;
    if (n >= N_NODES) return;

    const float4* eq = (const float4*)g_embQ;
    const float4* ek = (const float4*)g_embK;
    const float4* ev = (const float4*)g_embV;

    float4 aq = ((const float4*)bq)[t16];
    aq.x *= QK_SCALE; aq.y *= QK_SCALE; aq.z *= QK_SCALE; aq.w *= QK_SCALE;
    float4 ak = ((const float4*)bk)[t16];
    float4 av = ((const float4*)bv)[t16];

    #pragma unroll
    for (int f = 0; f < NFEAT; f++) {
        int idx = X[n * NFEAT + f] + c_offs[f];
        int base = idx * 16 + t16;
        float4 q = eq[base]; aq.x += q.x; aq.y += q.y; aq.z += q.z; aq.w += q.w;
        float4 k = ek[base]; ak.x += k.x; ak.y += k.y; ak.z += k.z; ak.w += k.w;
        float4 v = ev[base]; av.x += v.x; av.y += v.y; av.z += v.z; av.w += v.w;
    }
    ((float4*)g_Q)[n * 16 + t16] = aq;
    ((float4*)g_K)[n * 16 + t16] = ak;
    __half2* vh = (__half2*)(g_Vh + n * HDIM + t16 * 4);
    vh[0] = __floats2half2_rn(av.x, av.y);
    vh[1] = __floats2half2_rn(av.z, av.w);
}

// ---------------- K2: histogram of destination rows -------------------------
__global__ void k_hist(const int* __restrict__ row) {
    int e = blockIdx.x * blockDim.x + threadIdx.x;
    if (e < N_EDGES) atomicAdd(&g_cnt[row[e]], 1);
}

// ---------------- K3a: per-block sums (coalesced) ----------------------------
__global__ __launch_bounds__(SCAN_BS) void k_scan1() {
    __shared__ int ws[SCAN_BS / 32];
    int t = threadIdx.x, b = blockIdx.x;
    int idx = b * SCAN_BS + t;
    int v = (idx < N_NODES) ? g_cnt[idx] : 0;
    int s = v;
    #pragma unroll
    for (int o = 1; o < 32; o <<= 1) s += __shfl_xor_sync(0xffffffffu, s, o);
    if ((t & 31) == 0) ws[t >> 5] = s;
    __syncthreads();
    if (t == 0) {
        int tot = 0;
        #pragma unroll
        for (int i = 0; i < SCAN_BS / 32; i++) tot += ws[i];
        g_bsum[b] = tot;
    }
}

// ---------------- K3b: exclusive scan of 200 block sums ----------------------
__global__ __launch_bounds__(256) void k_scan2() {
    __shared__ int ws[8];
    int t = threadIdx.x;
    int lane = t & 31, wid = t >> 5;
    int v = (t < SCAN_NB) ? g_bsum[t] : 0;
    int inc = v;
    #pragma unroll
    for (int o = 1; o < 32; o <<= 1) {
        int y = __shfl_up_sync(0xffffffffu, inc, o);
        if (lane >= o) inc += y;
    }
    if (lane == 31) ws[wid] = inc;
    __syncthreads();
    if (wid == 0) {                       // ALL 32 lanes execute the shuffles
        int x = (lane < 8) ? ws[lane] : 0;
        #pragma unroll
        for (int o = 1; o < 8; o <<= 1) {
            int y = __shfl_up_sync(0xffffffffu, x, o);
            if (lane >= o) x += y;
        }
        if (lane < 8) ws[lane] = x;
    }
    __syncthreads();
    int off = (wid > 0) ? ws[wid - 1] : 0;
    if (t < SCAN_NB) g_boff[t] = off + inc - v;   // exclusive
}

// ---------------- K3c: block exclusive scan + global offset -----------------
__global__ __launch_bounds__(SCAN_BS) void k_scan3() {
    __shared__ int ws[SCAN_BS / 32];
    int t = threadIdx.x, b = blockIdx.x;
    int lane = t & 31, wid = t >> 5;
    int idx = b * SCAN_BS + t;
    int v = (idx < N_NODES) ? g_cnt[idx] : 0;
    int inc = v;
    #pragma unroll
    for (int o = 1; o < 32; o <<= 1) {
        int y = __shfl_up_sync(0xffffffffu, inc, o);
        if (lane >= o) inc += y;
    }
    if (lane == 31) ws[wid] = inc;
    __syncthreads();
    if (wid == 0) {                       // ALL 32 lanes execute the shuffles
        int x = (lane < SCAN_BS / 32) ? ws[lane] : 0;
        #pragma unroll
        for (int o = 1; o < SCAN_BS / 32; o <<= 1) {
            int y = __shfl_up_sync(0xffffffffu, x, o);
            if (lane >= o) x += y;
        }
        if (lane < SCAN_BS / 32) ws[lane] = x;
    }
    __syncthreads();
    int off = g_boff[b] + ((wid > 0) ? ws[wid - 1] : 0);
    if (idx < N_NODES) {
        int ex = off + inc - v;
        g_rowptr[idx] = ex;
        g_wcur[idx]   = ex;
    }
}

// ---------------- K4: scatter col indices into CSR order --------------------
__global__ void k_scatter(const int* __restrict__ row, const int* __restrict__ col) {
    int e = blockIdx.x * blockDim.x + threadIdx.x;
    if (e >= N_EDGES) return;
    int r = row[e];
    int pos = atomicAdd(&g_wcur[r], 1);
    g_scol[pos] = col[e];
}

// ---------------- K5: fused SDDMM + softmax + SpMM, single pass --------------
// No max-subtraction: |score| <= ~55 in the extreme tail, exp(s) is fp32-safe,
// and exp(s)/sum(exp(s)) is mathematically identical to the max-shifted form.
// After the 3 xor-shuffles every lane holds the full dot products for its head
// pair (h0 = (2*lane)&7, h0+1), so it can accumulate its 2 output columns
// directly — zero intermediate arrays.
__global__ __launch_bounds__(256) void k_fused() {
    int g = blockIdx.x * blockDim.x + threadIdx.x;
    int n = g >> 5;
    if (n >= N_NODES) return;
    int lane = threadIdx.x & 31;
    int start = g_rowptr[n], len = g_cnt[n];
    int c0 = 2 * lane;

    float2 q = *(const float2*)(g_Q + n * HDIM + c0);

    float sum0 = 0.f, sum1 = 0.f;
    float2 acc = make_float2(0.f, 0.f);
    #pragma unroll 4
    for (int i = 0; i < len; i++) {
        int c = g_scol[start + i];
        float2 k = *(const float2*)(g_K + c * HDIM + c0);
        __half2 vh = *(const __half2*)(g_Vh + c * HDIM + c0);
        float s0 = q.x * k.x;
        float s1 = q.y * k.y;
        s0 += __shfl_xor_sync(0xffffffffu, s0, 4);
        s1 += __shfl_xor_sync(0xffffffffu, s1, 4);
        s0 += __shfl_xor_sync(0xffffffffu, s0, 8);
        s1 += __shfl_xor_sync(0xffffffffu, s1, 8);
        s0 += __shfl_xor_sync(0xffffffffu, s0, 16);
        s1 += __shfl_xor_sync(0xffffffffu, s1, 16);
        float p0 = __expf(s0);
        float p1 = __expf(s1);
        float2 v = __half22float2(vh);
        sum0 += p0; sum1 += p1;
        acc.x += p0 * v.x;
        acc.y += p1 * v.y;
    }
    if (len > 0) {
        acc.x *= (1.0f / sum0);
        acc.y *= (1.0f / sum1);
    }
    *(float2*)(g_AV + n * HDIM + c0) = acc;
}

// ---------------- K6: out = AV @ Wo + bo (Wo register-resident) -------------
__global__ __launch_bounds__(128) void k_out(const float* __restrict__ Wo,
                                             const float* __restrict__ bo,
                                             float* __restrict__ out) {
    int lane = threadIdx.x & 31;
    int wglobal = (blockIdx.x * blockDim.x + threadIdx.x) >> 5;
    int nwarps = (gridDim.x * blockDim.x) >> 5;

    float2 w[64];
    #pragma unroll
    for (int j = 0; j < 64; j++)
        w[j] = *(const float2*)(Wo + j * HDIM + 2 * lane);
    float2 b = *(const float2*)(bo + 2 * lane);

    for (int n = wglobal; n < N_NODES; n += nwarps) {
        float2 a = *(const float2*)(g_AV + n * HDIM + 2 * lane);
        float ax = a.x, ay = a.y;
        float2 acc = b;
        #pragma unroll
        for (int l = 0; l < 32; l++) {
            float x = __shfl_sync(0xffffffffu, ax, l);  // a[2l]
            float y = __shfl_sync(0xffffffffu, ay, l);  // a[2l+1]
            acc.x += x * w[2 * l].x + y * w[2 * l + 1].x;
            acc.y += x * w[2 * l].y + y * w[2 * l + 1].y;
        }
        *(float2*)(out + n * HDIM + 2 * lane) = acc;
    }
}

// ---------------- launch -----------------------------------------------------
extern "C" void kernel_launch(void* const* d_in, const int* in_sizes, int n_in,
                              void* d_out, int out_size) {
    const int*   X        = (const int*)  d_in[0];
    const int*   row      = (const int*)  d_in[1];
    const int*   col      = (const int*)  d_in[2];
    const float* atom_emb = (const float*)d_in[3];
    const float* Wq       = (const float*)d_in[4];
    const float* bq       = (const float*)d_in[5];
    const float* Wk       = (const float*)d_in[6];
    const float* bk       = (const float*)d_in[7];
    const float* Wv       = (const float*)d_in[8];
    const float* bv       = (const float*)d_in[9];
    const float* Wo       = (const float*)d_in[10];
    const float* bo       = (const float*)d_in[11];
    float* out = (float*)d_out;

    (void)in_sizes; (void)n_in; (void)out_size;

    k_zero_cnt<<<(N_NODES + 255) / 256, 256>>>();
    k_emb_gemm<<<N_EMB, 192>>>(atom_emb, Wq, Wk, Wv);
    k_node_qkv<<<(N_NODES * 16 + 255) / 256, 256>>>(X, bq, bk, bv);
    k_hist<<<(N_EDGES + 255) / 256, 256>>>(row);
    k_scan1<<<SCAN_NB, SCAN_BS>>>();
    k_scan2<<<1, 256>>>();
    k_scan3<<<SCAN_NB, SCAN_BS>>>();
    k_scatter<<<(N_EDGES + 255) / 256, 256>>>(row, col);
    k_fused<<<(N_NODES * 32 + 255) / 256, 256>>>();
    k_out<<<1184, 128>>>(Wo, bo, out);
}

// round 8
// speedup vs baseline: 3.1070x; 1.0758x over previous
#include <cuda_runtime.h>
#include <cuda_fp16.h>

#define N_NODES 100000
#define N_EDGES 1600000
#define HDIM    64
#define N_EMB   174   // sum of ATOM_DIMS
#define NFEAT   9
#define QK_SCALE 0.35355339059327373f  // 1/sqrt(8)

#define SCAN_NB   200
#define SCAN_BS   512   // 200*512 = 102400 >= N_NODES
#define ZERO_NB   391   // ceil(100000/256)
#define QKV_NB    6250  // 6250*256/16 = 100000 nodes exactly
#define HIST_NB   6250

__constant__ int c_offs[NFEAT] = {0, 119, 124, 136, 148, 158, 164, 170, 172};

// All node vectors live in head-major "p-order": p = (d&7)*8 + (d>>3)
// (self-inverse permutation). Applied once at emb-table build; everything
// downstream just uses contiguous p-order.

// ---------------- scratch (device globals; no allocations allowed) ----------
__device__ float  g_embQ[N_EMB * HDIM];
__device__ float  g_embK[N_EMB * HDIM];
__device__ float  g_embV[N_EMB * HDIM];
__device__ float  g_Q[N_NODES * HDIM];
__device__ float  g_K[N_NODES * HDIM];
__device__ __half g_Vh[N_NODES * HDIM];
__device__ __half g_AVh[N_NODES * HDIM];
__device__ int    g_cnt   [N_NODES];
__device__ int    g_rowptr[N_NODES];
__device__ int    g_wcur  [N_NODES];
__device__ int    g_scol  [N_EDGES];
__device__ int    g_bsum  [SCAN_NB];
__device__ int    g_boff  [SCAN_NB];

// ---------------- K_prep: zero histogram + permuted, bias-folded tables -----
__global__ void k_prep(const float* __restrict__ emb,
                       const float* __restrict__ Wq, const float* __restrict__ bq,
                       const float* __restrict__ Wk, const float* __restrict__ bk,
                       const float* __restrict__ Wv, const float* __restrict__ bv) {
    int b = blockIdx.x, t = threadIdx.x;
    if (b < ZERO_NB) {                       // zero the histogram
        int i = b * 256 + t;
        if (i < N_NODES) g_cnt[i] = 0;
        return;
    }
    int r = b - ZERO_NB;                     // emb row 0..173
    __shared__ float a[HDIM];
    if (t < HDIM) a[t] = emb[r * HDIM + t];
    __syncthreads();
    if (t >= 192) return;
    int mat = t >> 6, c = t & 63;
    const float* W = (mat == 0) ? Wq : (mat == 1) ? Wk : Wv;
    float acc = 0.f;
    #pragma unroll
    for (int j = 0; j < HDIM; j++) acc += a[j] * W[j * HDIM + c];
    // fold bias into the feature-0 rows (every node uses exactly one of them)
    if (r < 119) acc += ((mat == 0) ? bq : (mat == 1) ? bk : bv)[c];
    int p = ((c & 7) << 3) + (c >> 3);       // head-major position
    if (mat == 0)      g_embQ[r * HDIM + p] = acc * QK_SCALE;
    else if (mat == 1) g_embK[r * HDIM + p] = acc;
    else               g_embV[r * HDIM + p] = acc;
}

// ---------------- K_gather_hist: node Q/K/V gather-sum  ||  edge histogram --
__global__ void k_gather_hist(const int* __restrict__ X,
                              const int* __restrict__ row) {
    int b = blockIdx.x, t = threadIdx.x;
    if (b >= QKV_NB) {                       // histogram half of the grid
        int e = (b - QKV_NB) * 256 + t;
        if (e < N_EDGES) atomicAdd(&g_cnt[row[e]], 1);
        return;
    }
    int tid = b * 256 + t;
    int n = tid >> 4, t16 = tid & 15;        // 16 threads/node, float4 each

    const float4* eq = (const float4*)g_embQ;
    const float4* ek = (const float4*)g_embK;
    const float4* ev = (const float4*)g_embV;

    float4 aq = make_float4(0.f, 0.f, 0.f, 0.f);
    float4 ak = aq, av = aq;
    #pragma unroll
    for (int f = 0; f < NFEAT; f++) {
        int idx = X[n * NFEAT + f] + c_offs[f];
        int base = idx * 16 + t16;
        float4 q = eq[base]; aq.x += q.x; aq.y += q.y; aq.z += q.z; aq.w += q.w;
        float4 k = ek[base]; ak.x += k.x; ak.y += k.y; ak.z += k.z; ak.w += k.w;
        float4 v = ev[base]; av.x += v.x; av.y += v.y; av.z += v.z; av.w += v.w;
    }
    ((float4*)g_Q)[n * 16 + t16] = aq;
    ((float4*)g_K)[n * 16 + t16] = ak;
    __half2 v01 = __floats2half2_rn(av.x, av.y);
    __half2 v23 = __floats2half2_rn(av.z, av.w);
    uint2 o;
    o.x = *(unsigned*)&v01; o.y = *(unsigned*)&v23;
    *(uint2*)(g_Vh + n * HDIM + 4 * t16) = o;
}

// ---------------- K3a: per-block sums ----------------------------------------
__global__ __launch_bounds__(SCAN_BS) void k_scan1() {
    __shared__ int ws[SCAN_BS / 32];
    int t = threadIdx.x, b = blockIdx.x;
    int idx = b * SCAN_BS + t;
    int v = (idx < N_NODES) ? g_cnt[idx] : 0;
    int s = v;
    #pragma unroll
    for (int o = 1; o < 32; o <<= 1) s += __shfl_xor_sync(0xffffffffu, s, o);
    if ((t & 31) == 0) ws[t >> 5] = s;
    __syncthreads();
    if (t == 0) {
        int tot = 0;
        #pragma unroll
        for (int i = 0; i < SCAN_BS / 32; i++) tot += ws[i];
        g_bsum[b] = tot;
    }
}

// ---------------- K3b: exclusive scan of 200 block sums ----------------------
__global__ __launch_bounds__(256) void k_scan2() {
    __shared__ int ws[8];
    int t = threadIdx.x;
    int lane = t & 31, wid = t >> 5;
    int v = (t < SCAN_NB) ? g_bsum[t] : 0;
    int inc = v;
    #pragma unroll
    for (int o = 1; o < 32; o <<= 1) {
        int y = __shfl_up_sync(0xffffffffu, inc, o);
        if (lane >= o) inc += y;
    }
    if (lane == 31) ws[wid] = inc;
    __syncthreads();
    if (wid == 0) {                       // ALL 32 lanes execute the shuffles
        int x = (lane < 8) ? ws[lane] : 0;
        #pragma unroll
        for (int o = 1; o < 8; o <<= 1) {
            int y = __shfl_up_sync(0xffffffffu, x, o);
            if (lane >= o) x += y;
        }
        if (lane < 8) ws[lane] = x;
    }
    __syncthreads();
    int off = (wid > 0) ? ws[wid - 1] : 0;
    if (t < SCAN_NB) g_boff[t] = off + inc - v;   // exclusive
}

// ---------------- K3c: block exclusive scan + global offset -----------------
__global__ __launch_bounds__(SCAN_BS) void k_scan3() {
    __shared__ int ws[SCAN_BS / 32];
    int t = threadIdx.x, b = blockIdx.x;
    int lane = t & 31, wid = t >> 5;
    int idx = b * SCAN_BS + t;
    int v = (idx < N_NODES) ? g_cnt[idx] : 0;
    int inc = v;
    #pragma unroll
    for (int o = 1; o < 32; o <<= 1) {
        int y = __shfl_up_sync(0xffffffffu, inc, o);
        if (lane >= o) inc += y;
    }
    if (lane == 31) ws[wid] = inc;
    __syncthreads();
    if (wid == 0) {                       // ALL 32 lanes execute the shuffles
        int x = (lane < SCAN_BS / 32) ? ws[lane] : 0;
        #pragma unroll
        for (int o = 1; o < SCAN_BS / 32; o <<= 1) {
            int y = __shfl_up_sync(0xffffffffu, x, o);
            if (lane >= o) x += y;
        }
        if (lane < SCAN_BS / 32) ws[lane] = x;
    }
    __syncthreads();
    int off = g_boff[b] + ((wid > 0) ? ws[wid - 1] : 0);
    if (idx < N_NODES) {
        int ex = off + inc - v;
        g_rowptr[idx] = ex;
        g_wcur[idx]   = ex;
    }
}

// ---------------- K4: scatter col indices into CSR order --------------------
__global__ void k_scatter(const int* __restrict__ row, const int* __restrict__ col) {
    int e = blockIdx.x * blockDim.x + threadIdx.x;
    if (e >= N_EDGES) return;
    int r = row[e];
    int pos = atomicAdd(&g_wcur[r], 1);
    g_scol[pos] = col[e];
}

// ---------------- K5: fused SDDMM + softmax + SpMM, head-major ---------------
// 16 lanes per edge (2 edges per warp-iteration). Lane t (0..15) owns p-dims
// [4t, 4t+4) = half of head (t>>1). One xor-1 shuffle completes the head dot
// product; exp(s) is fp32-safe (|s| <= ~55 in the 1e-16 tail), and
// exp(s)/sum exp(s) == softmax exactly. Lane-local normalization; one xor-16
// reduction per node at the end.
__global__ __launch_bounds__(256) void k_fused() {
    int g = blockIdx.x * blockDim.x + threadIdx.x;
    int n = g >> 5;
    if (n >= N_NODES) return;
    int lane = threadIdx.x & 31;
    int slot = lane >> 4, t = lane & 15;
    int start = g_rowptr[n], len = g_cnt[n];

    float4 q = ((const float4*)(g_Q + n * HDIM))[t];

    float sum = 0.f;
    float4 acc = make_float4(0.f, 0.f, 0.f, 0.f);
    #pragma unroll 4
    for (int i = 0; i < len; i += 2) {
        int idx = i + slot;
        bool valid = idx < len;
        int c = g_scol[start + (valid ? idx : i)];
        float4 k = ((const float4*)(g_K + c * HDIM))[t];
        uint2 vraw = *(const uint2*)(g_Vh + c * HDIM + 4 * t);
        float s = q.x * k.x + q.y * k.y + q.z * k.z + q.w * k.w;
        s += __shfl_xor_sync(0xffffffffu, s, 1);   // pair -> full head dot
        float p = valid ? __expf(s) : 0.f;
        float2 v01 = __half22float2(*(__half2*)&vraw.x);
        float2 v23 = __half22float2(*(__half2*)&vraw.y);
        sum += p;
        acc.x += p * v01.x; acc.y += p * v01.y;
        acc.z += p * v23.x; acc.w += p * v23.y;
    }
    // combine the two edge slots
    sum   += __shfl_xor_sync(0xffffffffu, sum,   16);
    acc.x += __shfl_xor_sync(0xffffffffu, acc.x, 16);
    acc.y += __shfl_xor_sync(0xffffffffu, acc.y, 16);
    acc.z += __shfl_xor_sync(0xffffffffu, acc.z, 16);
    acc.w += __shfl_xor_sync(0xffffffffu, acc.w, 16);
    float inv = (len > 0) ? (1.0f / sum) : 0.f;
    if (lane < 16) {
        __half2 o01 = __floats2half2_rn(acc.x * inv, acc.y * inv);
        __half2 o23 = __floats2half2_rn(acc.z * inv, acc.w * inv);
        uint2 o;
        o.x = *(unsigned*)&o01; o.y = *(unsigned*)&o23;
        *(uint2*)(g_AVh + n * HDIM + 4 * t) = o;
    }
}

// ---------------- K6: out = AV @ Wo + bo (Wo register-resident, permuted) ---
__global__ __launch_bounds__(128) void k_out(const float* __restrict__ Wo,
                                             const float* __restrict__ bo,
                                             float* __restrict__ out) {
    int lane = threadIdx.x & 31;
    int wglobal = (blockIdx.x * blockDim.x + threadIdx.x) >> 5;
    int nwarps = (gridDim.x * blockDim.x) >> 5;

    // w[s] = Wo row for p-dim s, columns (2*lane, 2*lane+1)
    float2 w[64];
    #pragma unroll
    for (int s = 0; s < 64; s++) {
        int d = ((s & 7) << 3) + (s >> 3);   // inverse (= same) permutation
        w[s] = *(const float2*)(Wo + d * HDIM + 2 * lane);
    }
    float2 b = *(const float2*)(bo + 2 * lane);

    for (int n = wglobal; n < N_NODES; n += nwarps) {
        unsigned av = ((const unsigned*)(g_AVh + n * HDIM))[lane]; // p=2l,2l+1
        float2 acc = b;
        #pragma unroll
        for (int s = 0; s < 32; s++) {
            unsigned r = __shfl_sync(0xffffffffu, av, s);
            float2 a2 = __half22float2(*(__half2*)&r);
            acc.x += a2.x * w[2 * s].x + a2.y * w[2 * s + 1].x;
            acc.y += a2.x * w[2 * s].y + a2.y * w[2 * s + 1].y;
        }
        *(float2*)(out + n * HDIM + 2 * lane) = acc;
    }
}

// ---------------- launch -----------------------------------------------------
extern "C" void kernel_launch(void* const* d_in, const int* in_sizes, int n_in,
                              void* d_out, int out_size) {
    const int*   X        = (const int*)  d_in[0];
    const int*   row      = (const int*)  d_in[1];
    const int*   col      = (const int*)  d_in[2];
    const float* atom_emb = (const float*)d_in[3];
    const float* Wq       = (const float*)d_in[4];
    const float* bq       = (const float*)d_in[5];
    const float* Wk       = (const float*)d_in[6];
    const float* bk       = (const float*)d_in[7];
    const float* Wv       = (const float*)d_in[8];
    const float* bv       = (const float*)d_in[9];
    const float* Wo       = (const float*)d_in[10];
    const float* bo       = (const float*)d_in[11];
    float* out = (float*)d_out;

    (void)in_sizes; (void)n_in; (void)out_size;

    k_prep<<<ZERO_NB + N_EMB, 256>>>(atom_emb, Wq, bq, Wk, bk, Wv, bv);
    k_gather_hist<<<QKV_NB + HIST_NB, 256>>>(X, row);
    k_scan1<<<SCAN_NB, SCAN_BS>>>();
    k_scan2<<<1, 256>>>();
    k_scan3<<<SCAN_NB, SCAN_BS>>>();
    k_scatter<<<(N_EDGES + 255) / 256, 256>>>(row, col);
    k_fused<<<(N_NODES * 32 + 255) / 256, 256>>>();
    k_out<<<1184, 128>>>(Wo, bo, out);
}

// round 9
// speedup vs baseline: 3.2377x; 1.0421x over previous
#include <cuda_runtime.h>
#include <cuda_fp16.h>

#define N_NODES 100000
#define N_EDGES 1600000
#define HDIM    64
#define N_EMB   174   // sum of ATOM_DIMS
#define NFEAT   9
#define QK_SCALE 0.35355339059327373f  // 1/sqrt(8)

#define SCAN_NB   200
#define SCAN_BS   512   // 200*512 = 102400 >= N_NODES
#define ZERO_NB   391   // ceil(100000/256)
#define QKV_NB    6250  // 6250*256/16 = 100000 nodes exactly
#define HIST_NB   6250

__constant__ int c_offs[NFEAT] = {0, 119, 124, 136, 148, 158, 164, 170, 172};

// All node vectors live in head-major "p-order": p = (d&7)*8 + (d>>3)
// (self-inverse permutation). Applied once at emb-table build.

// ---------------- scratch (device globals; no allocations allowed) ----------
__device__ float    g_embQ[N_EMB * HDIM];
__device__ float    g_embK[N_EMB * HDIM];
__device__ float    g_embV[N_EMB * HDIM];
__device__ float    g_Q[N_NODES * HDIM];
__device__ float    g_K[N_NODES * HDIM];
__device__ __half   g_Vh[N_NODES * HDIM];
__device__ __half   g_AVh[N_NODES * HDIM];
__device__ int      g_cnt   [N_NODES];
__device__ int      g_rowptr[N_NODES];
__device__ int      g_wcur  [N_NODES];
__device__ int      g_scol  [N_EDGES];
__device__ unsigned g_pack  [SCAN_NB];   // decoupled-lookback state words

// ---------------- K_prep: zero hist+flags, permuted bias-folded tables ------
__global__ void k_prep(const float* __restrict__ emb,
                       const float* __restrict__ Wq, const float* __restrict__ bq,
                       const float* __restrict__ Wk, const float* __restrict__ bk,
                       const float* __restrict__ Wv, const float* __restrict__ bv) {
    int b = blockIdx.x, t = threadIdx.x;
    if (b < ZERO_NB) {                       // zero histogram + lookback flags
        int i = b * 256 + t;
        if (i < N_NODES) g_cnt[i] = 0;
        if (b == 0 && t < SCAN_NB) g_pack[t] = 0u;
        return;
    }
    int r = b - ZERO_NB;                     // emb row 0..173
    __shared__ float a[HDIM];
    if (t < HDIM) a[t] = emb[r * HDIM + t];
    __syncthreads();
    if (t >= 192) return;
    int mat = t >> 6, c = t & 63;
    const float* W = (mat == 0) ? Wq : (mat == 1) ? Wk : Wv;
    float acc = 0.f;
    #pragma unroll
    for (int j = 0; j < HDIM; j++) acc += a[j] * W[j * HDIM + c];
    // fold bias into the feature-0 rows (every node uses exactly one of them)
    if (r < 119) acc += ((mat == 0) ? bq : (mat == 1) ? bk : bv)[c];
    int p = ((c & 7) << 3) + (c >> 3);       // head-major position
    if (mat == 0)      g_embQ[r * HDIM + p] = acc * QK_SCALE;
    else if (mat == 1) g_embK[r * HDIM + p] = acc;
    else               g_embV[r * HDIM + p] = acc;
}

// ---------------- K_gather_hist: node Q/K/V gather-sum  ||  edge histogram --
__global__ void k_gather_hist(const int* __restrict__ X,
                              const int* __restrict__ row) {
    int b = blockIdx.x, t = threadIdx.x;
    if (b >= QKV_NB) {                       // histogram half of the grid
        int e = (b - QKV_NB) * 256 + t;
        if (e < N_EDGES) atomicAdd(&g_cnt[row[e]], 1);
        return;
    }
    int tid = b * 256 + t;
    int n = tid >> 4, t16 = tid & 15;        // 16 threads/node, float4 each

    const float4* eq = (const float4*)g_embQ;
    const float4* ek = (const float4*)g_embK;
    const float4* ev = (const float4*)g_embV;

    float4 aq = make_float4(0.f, 0.f, 0.f, 0.f);
    float4 ak = aq, av = aq;
    #pragma unroll
    for (int f = 0; f < NFEAT; f++) {
        int idx = X[n * NFEAT + f] + c_offs[f];
        int base = idx * 16 + t16;
        float4 q = eq[base]; aq.x += q.x; aq.y += q.y; aq.z += q.z; aq.w += q.w;
        float4 k = ek[base]; ak.x += k.x; ak.y += k.y; ak.z += k.z; ak.w += k.w;
        float4 v = ev[base]; av.x += v.x; av.y += v.y; av.z += v.z; av.w += v.w;
    }
    ((float4*)g_Q)[n * 16 + t16] = aq;
    ((float4*)g_K)[n * 16 + t16] = ak;
    __half2 v01 = __floats2half2_rn(av.x, av.y);
    __half2 v23 = __floats2half2_rn(av.z, av.w);
    uint2 o;
    o.x = *(unsigned*)&v01; o.y = *(unsigned*)&v23;
    *(uint2*)(g_Vh + n * HDIM + 4 * t16) = o;
}

// ---------------- K_scan: single-kernel decoupled-lookback exclusive scan ---
// pack word: state(2b)<<30 | value(30b). state: 1=aggregate, 2=inclusive.
// All 200 blocks are co-resident (grid << SM capacity) -> lookback is safe.
__global__ __launch_bounds__(SCAN_BS) void k_scan_lb() {
    __shared__ int ws[SCAN_BS / 32];
    __shared__ int s_prev;
    int t = threadIdx.x, b = blockIdx.x;
    int lane = t & 31, wid = t >> 5;
    int idx = b * SCAN_BS + t;
    int v = (idx < N_NODES) ? g_cnt[idx] : 0;
    int inc = v;
    #pragma unroll
    for (int o = 1; o < 32; o <<= 1) {
        int y = __shfl_up_sync(0xffffffffu, inc, o);
        if (lane >= o) inc += y;
    }
    if (lane == 31) ws[wid] = inc;
    __syncthreads();
    if (wid == 0) {                       // ALL 32 lanes execute the shuffles
        int x = (lane < SCAN_BS / 32) ? ws[lane] : 0;
        #pragma unroll
        for (int o = 1; o < SCAN_BS / 32; o <<= 1) {
            int y = __shfl_up_sync(0xffffffffu, x, o);
            if (lane >= o) x += y;
        }
        if (lane < SCAN_BS / 32) ws[lane] = x;
    }
    __syncthreads();
    int binc  = inc + ((wid > 0) ? ws[wid - 1] : 0);   // block-local inclusive
    int total = ws[SCAN_BS / 32 - 1];

    if (t == 0) {
        if (b == 0) {
            atomicExch(&g_pack[0], (2u << 30) | (unsigned)total);
            s_prev = 0;
        } else {
            atomicExch(&g_pack[b], (1u << 30) | (unsigned)total);
            int run = 0, pb = b - 1;
            while (true) {
                unsigned pk = atomicAdd(&g_pack[pb], 0u);
                unsigned st = pk >> 30;
                if (st == 0u) { __nanosleep(20); continue; }
                run += (int)(pk & 0x3FFFFFFFu);
                if (st == 2u) break;
                pb--;
            }
            atomicExch(&g_pack[b], (2u << 30) | (unsigned)(run + total));
            s_prev = run;
        }
    }
    __syncthreads();
    int ex = s_prev + binc - v;
    if (idx < N_NODES) {
        g_rowptr[idx] = ex;
        g_wcur[idx]   = ex;
    }
}

// ---------------- K4: scatter col indices into CSR order --------------------
__global__ void k_scatter(const int* __restrict__ row, const int* __restrict__ col) {
    int e = blockIdx.x * blockDim.x + threadIdx.x;
    if (e >= N_EDGES) return;
    int r = row[e];
    int pos = atomicAdd(&g_wcur[r], 1);
    g_scol[pos] = col[e];
}

// ---------------- K5: fused SDDMM + softmax + SpMM -------------------------
// 8 lanes per edge (4 edge slots/warp). Lane t (=head, 0..7) owns p-dims
// [8t, 8t+8): it computes its head's FULL dot product locally (no per-edge
// shuffle at all), exponentiates (fp32-safe: |s| <= ~55 in the 1e-16 tail;
// exp(s)/sum exp(s) == softmax exactly), and accumulates 8 output dims.
// One 18-shuffle slot-reduction per node at the end.
__global__ __launch_bounds__(256) void k_fused() {
    int g = blockIdx.x * blockDim.x + threadIdx.x;
    int n = g >> 5;
    if (n >= N_NODES) return;
    int lane = threadIdx.x & 31;
    int slot = lane >> 3, t = lane & 7;      // t = head index
    int start = g_rowptr[n], len = g_cnt[n];

    const float4* qp = (const float4*)(g_Q + n * HDIM + 8 * t);
    float4 q0 = qp[0], q1 = qp[1];

    float sum = 0.f;
    float a0 = 0.f, a1 = 0.f, a2 = 0.f, a3 = 0.f;
    float a4 = 0.f, a5 = 0.f, a6 = 0.f, a7 = 0.f;
    for (int i = 0; i < len; i += 4) {
        int idx = i + slot;
        bool valid = idx < len;
        int c = g_scol[start + (valid ? idx : i)];
        const float4* kp = (const float4*)(g_K + c * HDIM + 8 * t);
        float4 k0 = kp[0], k1 = kp[1];
        uint4 vr = *(const uint4*)(g_Vh + c * HDIM + 8 * t);
        float s = q0.x * k0.x + q0.y * k0.y + q0.z * k0.z + q0.w * k0.w
                + q1.x * k1.x + q1.y * k1.y + q1.z * k1.z + q1.w * k1.w;
        float p = valid ? __expf(s) : 0.f;
        sum += p;
        float2 v0 = __half22float2(*(__half2*)&vr.x);
        float2 v1 = __half22float2(*(__half2*)&vr.y);
        float2 v2 = __half22float2(*(__half2*)&vr.z);
        float2 v3 = __half22float2(*(__half2*)&vr.w);
        a0 += p * v0.x; a1 += p * v0.y;
        a2 += p * v1.x; a3 += p * v1.y;
        a4 += p * v2.x; a5 += p * v2.y;
        a6 += p * v3.x; a7 += p * v3.y;
    }
    // reduce the 4 edge slots (same head t lives at lane = slot*8 + t)
    #pragma unroll
    for (int o = 8; o <= 16; o <<= 1) {
        sum += __shfl_xor_sync(0xffffffffu, sum, o);
        a0  += __shfl_xor_sync(0xffffffffu, a0, o);
        a1  += __shfl_xor_sync(0xffffffffu, a1, o);
        a2  += __shfl_xor_sync(0xffffffffu, a2, o);
        a3  += __shfl_xor_sync(0xffffffffu, a3, o);
        a4  += __shfl_xor_sync(0xffffffffu, a4, o);
        a5  += __shfl_xor_sync(0xffffffffu, a5, o);
        a6  += __shfl_xor_sync(0xffffffffu, a6, o);
        a7  += __shfl_xor_sync(0xffffffffu, a7, o);
    }
    float inv = (len > 0) ? (1.0f / sum) : 0.f;
    if (slot == 0) {
        __half2 h0 = __floats2half2_rn(a0 * inv, a1 * inv);
        __half2 h1 = __floats2half2_rn(a2 * inv, a3 * inv);
        __half2 h2 = __floats2half2_rn(a4 * inv, a5 * inv);
        __half2 h3 = __floats2half2_rn(a6 * inv, a7 * inv);
        uint4 o;
        o.x = *(unsigned*)&h0; o.y = *(unsigned*)&h1;
        o.z = *(unsigned*)&h2; o.w = *(unsigned*)&h3;
        *(uint4*)(g_AVh + n * HDIM + 8 * t) = o;
    }
}

// ---------------- K6: out = AV @ Wo + bo (Wo register-resident, permuted) ---
__global__ __launch_bounds__(128) void k_out(const float* __restrict__ Wo,
                                             const float* __restrict__ bo,
                                             float* __restrict__ out) {
    int lane = threadIdx.x & 31;
    int wglobal = (blockIdx.x * blockDim.x + threadIdx.x) >> 5;
    int nwarps = (gridDim.x * blockDim.x) >> 5;

    // w[s] = Wo row for p-dim s, columns (2*lane, 2*lane+1)
    float2 w[64];
    #pragma unroll
    for (int s = 0; s < 64; s++) {
        int d = ((s & 7) << 3) + (s >> 3);   // inverse (= same) permutation
        w[s] = *(const float2*)(Wo + d * HDIM + 2 * lane);
    }
    float2 b = *(const float2*)(bo + 2 * lane);

    for (int n = wglobal; n < N_NODES; n += nwarps) {
        unsigned av = ((const unsigned*)(g_AVh + n * HDIM))[lane]; // p=2l,2l+1
        float2 acc = b;
        #pragma unroll
        for (int s = 0; s < 32; s++) {
            unsigned r = __shfl_sync(0xffffffffu, av, s);
            float2 a2 = __half22float2(*(__half2*)&r);
            acc.x += a2.x * w[2 * s].x + a2.y * w[2 * s + 1].x;
            acc.y += a2.x * w[2 * s].y + a2.y * w[2 * s + 1].y;
        }
        *(float2*)(out + n * HDIM + 2 * lane) = acc;
    }
}

// ---------------- launch -----------------------------------------------------
extern "C" void kernel_launch(void* const* d_in, const int* in_sizes, int n_in,
                              void* d_out, int out_size) {
    const int*   X        = (const int*)  d_in[0];
    const int*   row      = (const int*)  d_in[1];
    const int*   col      = (const int*)  d_in[2];
    const float* atom_emb = (const float*)d_in[3];
    const float* Wq       = (const float*)d_in[4];
    const float* bq       = (const float*)d_in[5];
    const float* Wk       = (const float*)d_in[6];
    const float* bk       = (const float*)d_in[7];
    const float* Wv       = (const float*)d_in[8];
    const float* bv       = (const float*)d_in[9];
    const float* Wo       = (const float*)d_in[10];
    const float* bo       = (const float*)d_in[11];
    float* out = (float*)d_out;

    (void)in_sizes; (void)n_in; (void)out_size;

    k_prep<<<ZERO_NB + N_EMB, 256>>>(atom_emb, Wq, bq, Wk, bk, Wv, bv);
    k_gather_hist<<<QKV_NB + HIST_NB, 256>>>(X, row);
    k_scan_lb<<<SCAN_NB, SCAN_BS>>>();
    k_scatter<<<(N_EDGES + 255) / 256, 256>>>(row, col);
    k_fused<<<(N_NODES * 32 + 255) / 256, 256>>>();
    k_out<<<1184, 128>>>(Wo, bo, out);
}

// round 10
// speedup vs baseline: 3.4638x; 1.0698x over previous
#include <cuda_runtime.h>
#include <cuda_fp16.h>

#define N_NODES 100000
#define N_EDGES 1600000
#define HDIM    64
#define N_EMB   174   // sum of ATOM_DIMS
#define NFEAT   9
#define QK_SCALE 0.35355339059327373f  // 1/sqrt(8)

#define MAXDEG  96    // P(Binomial(1.6M,1e-5) > 96) ~ 1e-40 — never trips
#define ZERO_NB 391   // ceil(100000/256)
#define QKV_NB  6250  // 6250*256/16 = 100000 nodes exactly
#define EDGE_NB 6250

__constant__ int c_offs[NFEAT] = {0, 119, 124, 136, 148, 158, 164, 170, 172};

// All node vectors live in head-major "p-order": p = (d&7)*8 + (d>>3)
// (self-inverse permutation). Applied once at emb-table build.

// ---------------- scratch (device globals; no allocations allowed) ----------
__device__ float    g_embQ[N_EMB * HDIM];
__device__ float    g_embK[N_EMB * HDIM];
__device__ float    g_embV[N_EMB * HDIM];
__device__ float    g_Q[N_NODES * HDIM];
__device__ float    g_K[N_NODES * HDIM];
__device__ __half   g_Vh[N_NODES * HDIM];
__device__ __half   g_AVh[N_NODES * HDIM];
__device__ int      g_cnt [N_NODES];
__device__ int      g_scol[(size_t)N_NODES * MAXDEG];  // fixed-stride adjacency

// ---------------- K_prep: zero degree counters + permuted bias-folded tables
__global__ void k_prep(const float* __restrict__ emb,
                       const float* __restrict__ Wq, const float* __restrict__ bq,
                       const float* __restrict__ Wk, const float* __restrict__ bk,
                       const float* __restrict__ Wv, const float* __restrict__ bv) {
    int b = blockIdx.x, t = threadIdx.x;
    if (b < ZERO_NB) {                       // zero the degree counters
        int i = b * 256 + t;
        if (i < N_NODES) g_cnt[i] = 0;
        return;
    }
    int r = b - ZERO_NB;                     // emb row 0..173
    __shared__ float a[HDIM];
    if (t < HDIM) a[t] = emb[r * HDIM + t];
    __syncthreads();
    if (t >= 192) return;
    int mat = t >> 6, c = t & 63;
    const float* W = (mat == 0) ? Wq : (mat == 1) ? Wk : Wv;
    float acc = 0.f;
    #pragma unroll
    for (int j = 0; j < HDIM; j++) acc += a[j] * W[j * HDIM + c];
    // fold bias into the feature-0 rows (every node uses exactly one of them)
    if (r < 119) acc += ((mat == 0) ? bq : (mat == 1) ? bk : bv)[c];
    int p = ((c & 7) << 3) + (c >> 3);       // head-major position
    if (mat == 0)      g_embQ[r * HDIM + p] = acc * QK_SCALE;
    else if (mat == 1) g_embK[r * HDIM + p] = acc;
    else               g_embV[r * HDIM + p] = acc;
}

// ---------------- K_gather_scatter: node QKV gather  ||  edge adjacency -----
// Edge half builds the fixed-stride adjacency directly: atomicAdd on the
// per-node counter IS the slot index — no histogram, no scan, no rowptr.
__global__ void k_gather_scatter(const int* __restrict__ X,
                                 const int* __restrict__ row,
                                 const int* __restrict__ col) {
    int b = blockIdx.x, t = threadIdx.x;
    if (b >= QKV_NB) {                       // adjacency half of the grid
        int e = (b - QKV_NB) * 256 + t;
        if (e < N_EDGES) {
            int r = row[e];
            int pos = atomicAdd(&g_cnt[r], 1);
            if (pos < MAXDEG) g_scol[(size_t)r * MAXDEG + pos] = col[e];
        }
        return;
    }
    int tid = b * 256 + t;
    int n = tid >> 4, t16 = tid & 15;        // 16 threads/node, float4 each

    const float4* eq = (const float4*)g_embQ;
    const float4* ek = (const float4*)g_embK;
    const float4* ev = (const float4*)g_embV;

    float4 aq = make_float4(0.f, 0.f, 0.f, 0.f);
    float4 ak = aq, av = aq;
    #pragma unroll
    for (int f = 0; f < NFEAT; f++) {
        int idx = X[n * NFEAT + f] + c_offs[f];
        int base = idx * 16 + t16;
        float4 q = eq[base]; aq.x += q.x; aq.y += q.y; aq.z += q.z; aq.w += q.w;
        float4 k = ek[base]; ak.x += k.x; ak.y += k.y; ak.z += k.z; ak.w += k.w;
        float4 v = ev[base]; av.x += v.x; av.y += v.y; av.z += v.z; av.w += v.w;
    }
    ((float4*)g_Q)[n * 16 + t16] = aq;
    ((float4*)g_K)[n * 16 + t16] = ak;
    __half2 v01 = __floats2half2_rn(av.x, av.y);
    __half2 v23 = __floats2half2_rn(av.z, av.w);
    uint2 o;
    o.x = *(unsigned*)&v01; o.y = *(unsigned*)&v23;
    *(uint2*)(g_Vh + n * HDIM + 4 * t16) = o;
}

// ---------------- K_fused: SDDMM + softmax + SpMM (16 lanes/edge) -----------
// Lane t (0..15) owns p-dims [4t,4t+4) = half of head (t>>1); one LDG.128
// covers two full K rows (L1-wavefront floor). One xor-1 shuffle completes
// the head dot product. exp(s) is fp32-safe (|s| <= ~55 in the 1e-16 tail);
// exp(s)/sum exp(s) == softmax exactly. xor-16 slot reduction per node.
__global__ __launch_bounds__(256) void k_fused() {
    int g = blockIdx.x * blockDim.x + threadIdx.x;
    int n = g >> 5;
    if (n >= N_NODES) return;
    int lane = threadIdx.x & 31;
    int slot = lane >> 4, t = lane & 15;
    size_t base = (size_t)n * MAXDEG;
    int len = g_cnt[n];

    float4 q = ((const float4*)(g_Q + n * HDIM))[t];

    float sum = 0.f;
    float4 acc = make_float4(0.f, 0.f, 0.f, 0.f);
    #pragma unroll 4
    for (int i = 0; i < len; i += 2) {
        int idx = i + slot;
        bool valid = idx < len;
        int c = g_scol[base + (valid ? idx : i)];
        float4 k = ((const float4*)(g_K + c * HDIM))[t];
        uint2 vraw = *(const uint2*)(g_Vh + c * HDIM + 4 * t);
        float s = q.x * k.x + q.y * k.y + q.z * k.z + q.w * k.w;
        s += __shfl_xor_sync(0xffffffffu, s, 1);   // pair -> full head dot
        float p = valid ? __expf(s) : 0.f;
        float2 v01 = __half22float2(*(__half2*)&vraw.x);
        float2 v23 = __half22float2(*(__half2*)&vraw.y);
        sum += p;
        acc.x += p * v01.x; acc.y += p * v01.y;
        acc.z += p * v23.x; acc.w += p * v23.y;
    }
    // combine the two edge slots
    sum   += __shfl_xor_sync(0xffffffffu, sum,   16);
    acc.x += __shfl_xor_sync(0xffffffffu, acc.x, 16);
    acc.y += __shfl_xor_sync(0xffffffffu, acc.y, 16);
    acc.z += __shfl_xor_sync(0xffffffffu, acc.z, 16);
    acc.w += __shfl_xor_sync(0xffffffffu, acc.w, 16);
    float inv = (len > 0) ? (1.0f / sum) : 0.f;
    if (lane < 16) {
        __half2 o01 = __floats2half2_rn(acc.x * inv, acc.y * inv);
        __half2 o23 = __floats2half2_rn(acc.z * inv, acc.w * inv);
        uint2 o;
        o.x = *(unsigned*)&o01; o.y = *(unsigned*)&o23;
        *(uint2*)(g_AVh + n * HDIM + 4 * t) = o;
    }
}

// ---------------- K_out: out = AV @ Wo + bo (Wo register-resident, permuted)
__global__ __launch_bounds__(128) void k_out(const float* __restrict__ Wo,
                                             const float* __restrict__ bo,
                                             float* __restrict__ out) {
    int lane = threadIdx.x & 31;
    int wglobal = (blockIdx.x * blockDim.x + threadIdx.x) >> 5;
    int nwarps = (gridDim.x * blockDim.x) >> 5;

    // w[s] = Wo row for p-dim s, columns (2*lane, 2*lane+1)
    float2 w[64];
    #pragma unroll
    for (int s = 0; s < 64; s++) {
        int d = ((s & 7) << 3) + (s >> 3);   // inverse (= same) permutation
        w[s] = *(const float2*)(Wo + d * HDIM + 2 * lane);
    }
    float2 b = *(const float2*)(bo + 2 * lane);

    for (int n = wglobal; n < N_NODES; n += nwarps) {
        unsigned av = ((const unsigned*)(g_AVh + n * HDIM))[lane]; // p=2l,2l+1
        float2 acc = b;
        #pragma unroll
        for (int s = 0; s < 32; s++) {
            unsigned r = __shfl_sync(0xffffffffu, av, s);
            float2 a2 = __half22float2(*(__half2*)&r);
            acc.x += a2.x * w[2 * s].x + a2.y * w[2 * s + 1].x;
            acc.y += a2.x * w[2 * s].y + a2.y * w[2 * s + 1].y;
        }
        *(float2*)(out + n * HDIM + 2 * lane) = acc;
    }
}

// ---------------- launch -----------------------------------------------------
extern "C" void kernel_launch(void* const* d_in, const int* in_sizes, int n_in,
                              void* d_out, int out_size) {
    const int*   X        = (const int*)  d_in[0];
    const int*   row      = (const int*)  d_in[1];
    const int*   col      = (const int*)  d_in[2];
    const float* atom_emb = (const float*)d_in[3];
    const float* Wq       = (const float*)d_in[4];
    const float* bq       = (const float*)d_in[5];
    const float* Wk       = (const float*)d_in[6];
    const float* bk       = (const float*)d_in[7];
    const float* Wv       = (const float*)d_in[8];
    const float* bv       = (const float*)d_in[9];
    const float* Wo       = (const float*)d_in[10];
    const float* bo       = (const float*)d_in[11];
    float* out = (float*)d_out;

    (void)in_sizes; (void)n_in; (void)out_size;

    k_prep<<<ZERO_NB + N_EMB, 256>>>(atom_emb, Wq, bq, Wk, bk, Wv, bv);
    k_gather_scatter<<<QKV_NB + EDGE_NB, 256>>>(X, row, col);
    k_fused<<<(N_NODES * 32 + 255) / 256, 256>>>();
    k_out<<<1184, 128>>>(Wo, bo, out);
}

// round 11
// speedup vs baseline: 3.9181x; 1.1312x over previous
#include <cuda_runtime.h>
#include <cuda_fp16.h>

#define N_NODES 100000
#define N_EDGES 1600000
#define HDIM    64
#define N_EMB   174   // sum of ATOM_DIMS
#define NFEAT   9
#define QK_SCALE 0.35355339059327373f  // 1/sqrt(8)

#define MAXDEG  96    // P(Binomial(1.6M,1e-5) > 96) ~ 1e-40 — never trips
#define ZERO_NB 391   // ceil(100000/256)
#define QKV_NB  6250  // 6250*256/16 = 100000 nodes exactly
#define EDGE_NB 6250

#define OUT_TILE 128
#define OUT_NB   782  // ceil(100000/128)

__constant__ int c_offs[NFEAT] = {0, 119, 124, 136, 148, 158, 164, 170, 172};

// All node vectors live in head-major "p-order": p = (d&7)*8 + (d>>3)
// (self-inverse permutation). Applied once at emb-table build.

// ---------------- scratch (device globals; no allocations allowed) ----------
__device__ float    g_embQ[N_EMB * HDIM];
__device__ float    g_embK[N_EMB * HDIM];
__device__ float    g_embV[N_EMB * HDIM];
__device__ float    g_Q[N_NODES * HDIM];
__device__ float    g_K[N_NODES * HDIM];
__device__ __half   g_Vh[N_NODES * HDIM];
__device__ __half   g_AVh[N_NODES * HDIM];
__device__ int      g_cnt [N_NODES];
__device__ int      g_scol[(size_t)N_NODES * MAXDEG];  // fixed-stride adjacency

// ---------------- K_prep: zero degree counters + permuted bias-folded tables
__global__ void k_prep(const float* __restrict__ emb,
                       const float* __restrict__ Wq, const float* __restrict__ bq,
                       const float* __restrict__ Wk, const float* __restrict__ bk,
                       const float* __restrict__ Wv, const float* __restrict__ bv) {
    int b = blockIdx.x, t = threadIdx.x;
    if (b < ZERO_NB) {                       // zero the degree counters
        int i = b * 256 + t;
        if (i < N_NODES) g_cnt[i] = 0;
        return;
    }
    int r = b - ZERO_NB;                     // emb row 0..173
    __shared__ float a[HDIM];
    if (t < HDIM) a[t] = emb[r * HDIM + t];
    __syncthreads();
    if (t >= 192) return;
    int mat = t >> 6, c = t & 63;
    const float* W = (mat == 0) ? Wq : (mat == 1) ? Wk : Wv;
    float acc = 0.f;
    #pragma unroll
    for (int j = 0; j < HDIM; j++) acc += a[j] * W[j * HDIM + c];
    // fold bias into the feature-0 rows (every node uses exactly one of them)
    if (r < 119) acc += ((mat == 0) ? bq : (mat == 1) ? bk : bv)[c];
    int p = ((c & 7) << 3) + (c >> 3);       // head-major position
    if (mat == 0)      g_embQ[r * HDIM + p] = acc * QK_SCALE;
    else if (mat == 1) g_embK[r * HDIM + p] = acc;
    else               g_embV[r * HDIM + p] = acc;
}

// ---------------- K_gather_scatter: node QKV gather  ||  edge adjacency -----
__global__ void k_gather_scatter(const int* __restrict__ X,
                                 const int* __restrict__ row,
                                 const int* __restrict__ col) {
    int b = blockIdx.x, t = threadIdx.x;
    if (b >= QKV_NB) {                       // adjacency half of the grid
        int e = (b - QKV_NB) * 256 + t;
        if (e < N_EDGES) {
            int r = row[e];
            int pos = atomicAdd(&g_cnt[r], 1);
            if (pos < MAXDEG) g_scol[(size_t)r * MAXDEG + pos] = col[e];
        }
        return;
    }
    int tid = b * 256 + t;
    int n = tid >> 4, t16 = tid & 15;        // 16 threads/node, float4 each

    const float4* eq = (const float4*)g_embQ;
    const float4* ek = (const float4*)g_embK;
    const float4* ev = (const float4*)g_embV;

    float4 aq = make_float4(0.f, 0.f, 0.f, 0.f);
    float4 ak = aq, av = aq;
    #pragma unroll
    for (int f = 0; f < NFEAT; f++) {
        int idx = X[n * NFEAT + f] + c_offs[f];
        int base = idx * 16 + t16;
        float4 q = eq[base]; aq.x += q.x; aq.y += q.y; aq.z += q.z; aq.w += q.w;
        float4 k = ek[base]; ak.x += k.x; ak.y += k.y; ak.z += k.z; ak.w += k.w;
        float4 v = ev[base]; av.x += v.x; av.y += v.y; av.z += v.z; av.w += v.w;
    }
    ((float4*)g_Q)[n * 16 + t16] = aq;
    ((float4*)g_K)[n * 16 + t16] = ak;
    __half2 v01 = __floats2half2_rn(av.x, av.y);
    __half2 v23 = __floats2half2_rn(av.z, av.w);
    uint2 o;
    o.x = *(unsigned*)&v01; o.y = *(unsigned*)&v23;
    *(uint2*)(g_Vh + n * HDIM + 4 * t16) = o;
}

// ---------------- K_fused: SDDMM + softmax + SpMM (16 lanes/edge) -----------
__global__ __launch_bounds__(256) void k_fused() {
    int g = blockIdx.x * blockDim.x + threadIdx.x;
    int n = g >> 5;
    if (n >= N_NODES) return;
    int lane = threadIdx.x & 31;
    int slot = lane >> 4, t = lane & 15;
    size_t base = (size_t)n * MAXDEG;
    int len = g_cnt[n];

    float4 q = ((const float4*)(g_Q + n * HDIM))[t];

    float sum = 0.f;
    float4 acc = make_float4(0.f, 0.f, 0.f, 0.f);
    #pragma unroll 4
    for (int i = 0; i < len; i += 2) {
        int idx = i + slot;
        bool valid = idx < len;
        int c = g_scol[base + (valid ? idx : i)];
        float4 k = ((const float4*)(g_K + c * HDIM))[t];
        uint2 vraw = *(const uint2*)(g_Vh + c * HDIM + 4 * t);
        float s = q.x * k.x + q.y * k.y + q.z * k.z + q.w * k.w;
        s += __shfl_xor_sync(0xffffffffu, s, 1);   // pair -> full head dot
        float p = valid ? __expf(s) : 0.f;
        float2 v01 = __half22float2(*(__half2*)&vraw.x);
        float2 v23 = __half22float2(*(__half2*)&vraw.y);
        sum += p;
        acc.x += p * v01.x; acc.y += p * v01.y;
        acc.z += p * v23.x; acc.w += p * v23.y;
    }
    sum   += __shfl_xor_sync(0xffffffffu, sum,   16);
    acc.x += __shfl_xor_sync(0xffffffffu, acc.x, 16);
    acc.y += __shfl_xor_sync(0xffffffffu, acc.y, 16);
    acc.z += __shfl_xor_sync(0xffffffffu, acc.z, 16);
    acc.w += __shfl_xor_sync(0xffffffffu, acc.w, 16);
    float inv = (len > 0) ? (1.0f / sum) : 0.f;
    if (lane < 16) {
        __half2 o01 = __floats2half2_rn(acc.x * inv, acc.y * inv);
        __half2 o23 = __floats2half2_rn(acc.z * inv, acc.w * inv);
        uint2 o;
        o.x = *(unsigned*)&o01; o.y = *(unsigned*)&o23;
        *(uint2*)(g_AVh + n * HDIM + 4 * t) = o;
    }
}

// ---------------- K_out: tiled GEMM  out = AV @ Wo + bo ---------------------
// Block = 256 threads, tile = 128 nodes x all 64 cols. Wo staged in shared
// fp32 with the p-order permutation applied to its row index; AV tile staged
// as half2. Thread (tc,tm) computes 8 nodes x 4 cols: per k-pair, 2 float4
// W loads (half-warp broadcast) + 8 half2 A loads (16-lane broadcast) feed
// 64 FFMA — no shuffles, ~60 regs, 4 blocks/SM.
__global__ __launch_bounds__(256) void k_out(const float* __restrict__ Wo,
                                             const float* __restrict__ bo,
                                             float* __restrict__ out) {
    __shared__ float   Ws[HDIM][68];          // [k_p][c], padded row = 272B
    __shared__ __half2 As[OUT_TILE][33];      // [node][k2], padded
    __shared__ float   bo_s[HDIM];

    int t = threadIdx.x;
    int nb = blockIdx.x * OUT_TILE;

    // stage Wo with row permutation: Ws[p(d)][c] = Wo[d][c]
    #pragma unroll
    for (int j = 0; j < 16; j++) {
        int idx = t + 256 * j;                // 4096 elements
        int d = idx >> 6, c = idx & 63;
        int p = ((d & 7) << 3) + (d >> 3);
        Ws[p][c] = Wo[idx];
    }
    if (t < HDIM) bo_s[t] = bo[t];

    // stage AV tile (half2, coalesced)
    #pragma unroll
    for (int j = 0; j < 16; j++) {
        int idx = t + 256 * j;                // 4096 half2
        int r = idx >> 5, k2 = idx & 31;
        __half2 h = (nb + r < N_NODES)
                  ? ((const __half2*)g_AVh)[(size_t)(nb + r) * 32 + k2]
                  : __half2(__float2half(0.f), __float2half(0.f));
        As[r][k2] = h;
    }
    __syncthreads();

    int tc = t & 15, tm = t >> 4;             // cols 4tc.., nodes 8tm..
    float4 bias = *(const float4*)&bo_s[4 * tc];
    float4 acc[8];
    #pragma unroll
    for (int i = 0; i < 8; i++) acc[i] = bias;

    #pragma unroll 8
    for (int k2 = 0; k2 < 32; k2++) {
        int k = 2 * k2;
        float4 w0 = *(const float4*)&Ws[k][4 * tc];
        float4 w1 = *(const float4*)&Ws[k + 1][4 * tc];
        #pragma unroll
        for (int i = 0; i < 8; i++) {
            float2 a = __half22float2(As[8 * tm + i][k2]);
            acc[i].x += a.x * w0.x + a.y * w1.x;
            acc[i].y += a.x * w0.y + a.y * w1.y;
            acc[i].z += a.x * w0.z + a.y * w1.z;
            acc[i].w += a.x * w0.w + a.y * w1.w;
        }
    }

    #pragma unroll
    for (int i = 0; i < 8; i++) {
        int n = nb + 8 * tm + i;
        if (n < N_NODES)
            *(float4*)&out[(size_t)n * HDIM + 4 * tc] = acc[i];
    }
}

// ---------------- launch -----------------------------------------------------
extern "C" void kernel_launch(void* const* d_in, const int* in_sizes, int n_in,
                              void* d_out, int out_size) {
    const int*   X        = (const int*)  d_in[0];
    const int*   row      = (const int*)  d_in[1];
    const int*   col      = (const int*)  d_in[2];
    const float* atom_emb = (const float*)d_in[3];
    const float* Wq       = (const float*)d_in[4];
    const float* bq       = (const float*)d_in[5];
    const float* Wk       = (const float*)d_in[6];
    const float* bk       = (const float*)d_in[7];
    const float* Wv       = (const float*)d_in[8];
    const float* bv       = (const float*)d_in[9];
    const float* Wo       = (const float*)d_in[10];
    const float* bo       = (const float*)d_in[11];
    float* out = (float*)d_out;

    (void)in_sizes; (void)n_in; (void)out_size;

    k_prep<<<ZERO_NB + N_EMB, 256>>>(atom_emb, Wq, bq, Wk, bk, Wv, bv);
    k_gather_scatter<<<QKV_NB + EDGE_NB, 256>>>(X, row, col);
    k_fused<<<(N_NODES * 32 + 255) / 256, 256>>>();
    k_out<<<OUT_NB, 256>>>(Wo, bo, out);
}

// round 12
// speedup vs baseline: 4.3460x; 1.1092x over previous
#include <cuda_runtime.h>
#include <cuda_fp16.h>

#define N_NODES 100000
#define N_EDGES 1600000
#define HDIM    64
#define N_EMB   174   // sum of ATOM_DIMS
#define NFEAT   9
#define QK_SCALE 0.35355339059327373f  // 1/sqrt(8)

#define MAXDEG  96    // P(Binomial(1.6M,1e-5) > 96) ~ 1e-40 — never trips
#define ZERO_NB 391   // ceil(100000/256)
#define QKV_NB  6250  // 6250*256/16 = 100000 nodes exactly
#define EDGE_NB 6250
#define OUT_NB  1563  // ceil(100000/64)

__constant__ int c_offs[NFEAT] = {0, 119, 124, 136, 148, 158, 164, 170, 172};

// All node vectors live in head-major "p-order": p = (d&7)*8 + (d>>3)
// (self-inverse permutation). Applied once at emb-table build.

// ---------------- scratch (device globals; no allocations allowed) ----------
__device__ float    g_embQ[N_EMB * HDIM];
__device__ float    g_embK[N_EMB * HDIM];
__device__ float    g_embV[N_EMB * HDIM];
__device__ float    g_Q[N_NODES * HDIM];
__device__ float    g_K[N_NODES * HDIM];
__device__ __half   g_Vh[N_NODES * HDIM];
__device__ __half   g_AVh[N_NODES * HDIM];
__device__ int      g_cnt [N_NODES];
__device__ int      g_scol[(size_t)N_NODES * MAXDEG];  // fixed-stride adjacency
                                                       // (zero-init; unwritten slots = node 0, safe)

// ---------------- K_prep: zero degree counters + permuted bias-folded tables
__global__ void k_prep(const float* __restrict__ emb,
                       const float* __restrict__ Wq, const float* __restrict__ bq,
                       const float* __restrict__ Wk, const float* __restrict__ bk,
                       const float* __restrict__ Wv, const float* __restrict__ bv) {
    int b = blockIdx.x, t = threadIdx.x;
    if (b < ZERO_NB) {                       // zero the degree counters
        int i = b * 256 + t;
        if (i < N_NODES) g_cnt[i] = 0;
        return;
    }
    int r = b - ZERO_NB;                     // emb row 0..173
    __shared__ float a[HDIM];
    if (t < HDIM) a[t] = emb[r * HDIM + t];
    __syncthreads();
    if (t >= 192) return;
    int mat = t >> 6, c = t & 63;
    const float* W = (mat == 0) ? Wq : (mat == 1) ? Wk : Wv;
    float acc = 0.f;
    #pragma unroll
    for (int j = 0; j < HDIM; j++) acc += a[j] * W[j * HDIM + c];
    // fold bias into the feature-0 rows (every node uses exactly one of them)
    if (r < 119) acc += ((mat == 0) ? bq : (mat == 1) ? bk : bv)[c];
    int p = ((c & 7) << 3) + (c >> 3);       // head-major position
    if (mat == 0)      g_embQ[r * HDIM + p] = acc * QK_SCALE;
    else if (mat == 1) g_embK[r * HDIM + p] = acc;
    else               g_embV[r * HDIM + p] = acc;
}

// ---------------- K_gather_scatter: node QKV gather  ||  edge adjacency -----
__global__ void k_gather_scatter(const int* __restrict__ X,
                                 const int* __restrict__ row,
                                 const int* __restrict__ col) {
    int b = blockIdx.x, t = threadIdx.x;
    if (b >= QKV_NB) {                       // adjacency half of the grid
        int e = (b - QKV_NB) * 256 + t;
        if (e < N_EDGES) {
            int r = row[e];
            int pos = atomicAdd(&g_cnt[r], 1);
            if (pos < MAXDEG) g_scol[(size_t)r * MAXDEG + pos] = col[e];
        }
        return;
    }
    int tid = b * 256 + t;
    int n = tid >> 4, t16 = tid & 15;        // 16 threads/node, float4 each

    const float4* eq = (const float4*)g_embQ;
    const float4* ek = (const float4*)g_embK;
    const float4* ev = (const float4*)g_embV;

    float4 aq = make_float4(0.f, 0.f, 0.f, 0.f);
    float4 ak = aq, av = aq;
    #pragma unroll
    for (int f = 0; f < NFEAT; f++) {
        int idx = X[n * NFEAT + f] + c_offs[f];
        int base = idx * 16 + t16;
        float4 q = eq[base]; aq.x += q.x; aq.y += q.y; aq.z += q.z; aq.w += q.w;
        float4 k = ek[base]; ak.x += k.x; ak.y += k.y; ak.z += k.z; ak.w += k.w;
        float4 v = ev[base]; av.x += v.x; av.y += v.y; av.z += v.z; av.w += v.w;
    }
    ((float4*)g_Q)[n * 16 + t16] = aq;
    ((float4*)g_K)[n * 16 + t16] = ak;
    __half2 v01 = __floats2half2_rn(av.x, av.y);
    __half2 v23 = __floats2half2_rn(av.z, av.w);
    uint2 o;
    o.x = *(unsigned*)&v01; o.y = *(unsigned*)&v23;
    *(uint2*)(g_Vh + n * HDIM + 4 * t16) = o;
}

// ---------------- K_fused: SDDMM + softmax + SpMM (16 lanes/edge) -----------
// Adjacency row held in ONE register per warp (lane i holds scol[i], covers
// the first 32 edges — Poisson(16) makes len>32 a ~2e-4/node event, handled
// by an LDG fallback). Column index comes from SHFL.IDX, so the K/V gathers
// have no dependent-load prefix. exp(s) is fp32-safe; exp/sum == softmax.
__global__ __launch_bounds__(256) void k_fused() {
    int g = blockIdx.x * blockDim.x + threadIdx.x;
    int n = g >> 5;
    if (n >= N_NODES) return;
    int lane = threadIdx.x & 31;
    int slot = lane >> 4, t = lane & 15;
    size_t base = (size_t)n * MAXDEG;
    int len = min(g_cnt[n], MAXDEG);

    int c_reg = g_scol[base + lane];         // edges 0..31 (zero-init tail safe)
    float4 q = ((const float4*)(g_Q + n * HDIM))[t];

    float sum = 0.f;
    float4 acc = make_float4(0.f, 0.f, 0.f, 0.f);
    #pragma unroll 4
    for (int i = 0; i < len; i += 2) {
        int idx = i + slot;
        bool valid = idx < len;
        int c;
        if (i + 1 < 32) c = __shfl_sync(0xffffffffu, c_reg, idx);
        else            c = g_scol[base + (valid ? idx : i)];
        float4 k = ((const float4*)(g_K + c * HDIM))[t];
        uint2 vraw = *(const uint2*)(g_Vh + c * HDIM + 4 * t);
        float s = q.x * k.x + q.y * k.y + q.z * k.z + q.w * k.w;
        s += __shfl_xor_sync(0xffffffffu, s, 1);   // pair -> full head dot
        float p = valid ? __expf(s) : 0.f;
        float2 v01 = __half22float2(*(__half2*)&vraw.x);
        float2 v23 = __half22float2(*(__half2*)&vraw.y);
        sum += p;
        acc.x += p * v01.x; acc.y += p * v01.y;
        acc.z += p * v23.x; acc.w += p * v23.y;
    }
    sum   += __shfl_xor_sync(0xffffffffu, sum,   16);
    acc.x += __shfl_xor_sync(0xffffffffu, acc.x, 16);
    acc.y += __shfl_xor_sync(0xffffffffu, acc.y, 16);
    acc.z += __shfl_xor_sync(0xffffffffu, acc.z, 16);
    acc.w += __shfl_xor_sync(0xffffffffu, acc.w, 16);
    float inv = (len > 0) ? (1.0f / sum) : 0.f;
    if (lane < 16) {
        __half2 o01 = __floats2half2_rn(acc.x * inv, acc.y * inv);
        __half2 o23 = __floats2half2_rn(acc.z * inv, acc.w * inv);
        uint2 o;
        o.x = *(unsigned*)&o01; o.y = *(unsigned*)&o23;
        *(uint2*)(g_AVh + n * HDIM + 4 * t) = o;
    }
}

// ---------------- K_out: tensor-core GEMM  out = AV @ Wo + bo ---------------
// Block = 128 threads (4 warps), 64 nodes/block. A (fp16, p-order) and Wo
// (fp16, rows permuted to p-order) staged in shared; each warp computes a
// 16x64 tile via mma.sync.m16n8k16 (8 n-tiles x 4 k-steps), fp32 accum.
__global__ __launch_bounds__(128) void k_out(const float* __restrict__ Wo,
                                             const float* __restrict__ bo,
                                             float* __restrict__ out) {
    __shared__ __half Ws[HDIM][72];          // [k_p][c], pad -> conflict-free LDSM
    __shared__ __half As[64][72];            // [node][k_p]
    __shared__ float  bos[HDIM];

    int t = threadIdx.x;
    size_t nb = (size_t)blockIdx.x * 64;

    // stage Wo: permute rows to p-order, quantize fp16
    #pragma unroll
    for (int j = 0; j < 32; j++) {
        int idx = t + 128 * j;               // 4096 elements
        int d = idx >> 6, c = idx & 63;
        int p = ((d & 7) << 3) + (d >> 3);
        Ws[p][c] = __float2half(Wo[idx]);
    }
    if (t < HDIM) bos[t] = bo[t];

    // stage AV tile (coalesced half2)
    #pragma unroll
    for (int j = 0; j < 16; j++) {
        int idx = t + 128 * j;               // 2048 half2
        int r = idx >> 5, k2 = idx & 31;
        __half2 h = (nb + r < N_NODES)
                  ? ((const __half2*)g_AVh)[(nb + r) * 32 + k2]
                  : __float2half2_rn(0.f);
        *(__half2*)&As[r][2 * k2] = h;
    }
    __syncthreads();

    int w = t >> 5, l = t & 31;

    // A fragments: 4 k-steps of m16k16
    unsigned a[4][4];
    #pragma unroll
    for (int kk = 0; kk < 4; kk++) {
        unsigned addr = (unsigned)__cvta_generic_to_shared(
            &As[w * 16 + (l & 15)][kk * 16 + (l >> 4) * 8]);
        asm volatile("ldmatrix.sync.aligned.m8n8.x4.shared.b16 {%0,%1,%2,%3}, [%4];"
                     : "=r"(a[kk][0]), "=r"(a[kk][1]), "=r"(a[kk][2]), "=r"(a[kk][3])
                     : "r"(addr));
    }

    int g0 = l >> 2;                         // C-fragment row group
    int c0 = (l & 3) * 2;
    #pragma unroll
    for (int nt = 0; nt < 8; nt++) {
        float d0 = 0.f, d1 = 0.f, d2 = 0.f, d3 = 0.f;
        #pragma unroll
        for (int kk = 0; kk < 4; kk++) {
            unsigned b0, b1;
            unsigned baddr = (unsigned)__cvta_generic_to_shared(
                &Ws[kk * 16 + (l & 15)][nt * 8]);
            asm volatile("ldmatrix.sync.aligned.m8n8.x2.trans.shared.b16 {%0,%1}, [%2];"
                         : "=r"(b0), "=r"(b1) : "r"(baddr));
            asm volatile(
                "mma.sync.aligned.m16n8k16.row.col.f32.f16.f16.f32 "
                "{%0,%1,%2,%3},{%4,%5,%6,%7},{%8,%9},{%0,%1,%2,%3};"
                : "+f"(d0), "+f"(d1), "+f"(d2), "+f"(d3)
                : "r"(a[kk][0]), "r"(a[kk][1]), "r"(a[kk][2]), "r"(a[kk][3]),
                  "r"(b0), "r"(b1));
        }
        int cc = nt * 8 + c0;
        float bx = bos[cc], by = bos[cc + 1];
        size_t n0 = nb + w * 16 + g0;
        if (n0 < N_NODES)
            *(float2*)&out[n0 * HDIM + cc] = make_float2(d0 + bx, d1 + by);
        if (n0 + 8 < N_NODES)
            *(float2*)&out[(n0 + 8) * HDIM + cc] = make_float2(d2 + bx, d3 + by);
    }
}

// ---------------- launch -----------------------------------------------------
extern "C" void kernel_launch(void* const* d_in, const int* in_sizes, int n_in,
                              void* d_out, int out_size) {
    const int*   X        = (const int*)  d_in[0];
    const int*   row      = (const int*)  d_in[1];
    const int*   col      = (const int*)  d_in[2];
    const float* atom_emb = (const float*)d_in[3];
    const float* Wq       = (const float*)d_in[4];
    const float* bq       = (const float*)d_in[5];
    const float* Wk       = (const float*)d_in[6];
    const float* bk       = (const float*)d_in[7];
    const float* Wv       = (const float*)d_in[8];
    const float* bv       = (const float*)d_in[9];
    const float* Wo       = (const float*)d_in[10];
    const float* bo       = (const float*)d_in[11];
    float* out = (float*)d_out;

    (void)in_sizes; (void)n_in; (void)out_size;

    k_prep<<<ZERO_NB + N_EMB, 256>>>(atom_emb, Wq, bq, Wk, bk, Wv, bv);
    k_gather_scatter<<<QKV_NB + EDGE_NB, 256>>>(X, row, col);
    k_fused<<<(N_NODES * 32 + 255) / 256, 256>>>();
    k_out<<<OUT_NB, 128>>>(Wo, bo, out);
}

// round 13
// speedup vs baseline: 4.4075x; 1.0141x over previous
#include <cuda_runtime.h>
#include <cuda_fp16.h>

#define N_NODES 100000
#define N_EDGES 1600000
#define HDIM    64
#define N_EMB   174   // sum of ATOM_DIMS
#define NFEAT   9
#define QK_SCALE 0.35355339059327373f  // 1/sqrt(8)

#define MAXDEG  96    // P(Binomial(1.6M,1e-5) > 96) ~ 1e-40 — never trips
#define ZERO_NB 391   // ceil(100000/256)
#define WO_NB   16    // 16*256 = 4096 = Wo elements
#define QKV_NB  6250  // 6250*256/16 = 100000 nodes exactly
#define EDGE_NB 6250
#define OUT_NB  782   // ceil(100000/128)

__constant__ int c_offs[NFEAT] = {0, 119, 124, 136, 148, 158, 164, 170, 172};

// All node vectors live in head-major "p-order": p = (d&7)*8 + (d>>3)
// (self-inverse permutation). Applied once at emb-table build.

// ---------------- scratch (device globals; no allocations allowed) ----------
__device__ float    g_embQ[N_EMB * HDIM];
__device__ float    g_embK[N_EMB * HDIM];
__device__ float    g_embV[N_EMB * HDIM];
__device__ float    g_Q[N_NODES * HDIM];
__device__ float    g_K[N_NODES * HDIM];
__device__ __half   g_Vh[N_NODES * HDIM];
__device__ __half   g_AVh[N_NODES * HDIM];
__device__ __half   g_Woh[HDIM * HDIM];      // fp16, rows already permuted
__device__ int      g_cnt [N_NODES];
__device__ int      g_scol[(size_t)N_NODES * MAXDEG];  // fixed-stride adjacency
                                                       // (zero-init; unwritten slots = node 0, safe)

// ---------------- K_prep: zero counters + permuted tables + fp16 Wo ---------
__global__ void k_prep(const float* __restrict__ emb,
                       const float* __restrict__ Wq, const float* __restrict__ bq,
                       const float* __restrict__ Wk, const float* __restrict__ bk,
                       const float* __restrict__ Wv, const float* __restrict__ bv,
                       const float* __restrict__ Wo) {
    int b = blockIdx.x, t = threadIdx.x;
    if (b < ZERO_NB) {                       // zero the degree counters
        int i = b * 256 + t;
        if (i < N_NODES) g_cnt[i] = 0;
        return;
    }
    if (b < ZERO_NB + WO_NB) {               // pre-permute + quantize Wo
        int idx = (b - ZERO_NB) * 256 + t;   // d*64 + c
        int d = idx >> 6, c = idx & 63;
        int p = ((d & 7) << 3) + (d >> 3);
        g_Woh[p * HDIM + c] = __float2half(Wo[idx]);
        return;
    }
    int r = b - ZERO_NB - WO_NB;             // emb row 0..173
    __shared__ float a[HDIM];
    if (t < HDIM) a[t] = emb[r * HDIM + t];
    __syncthreads();
    if (t >= 192) return;
    int mat = t >> 6, c = t & 63;
    const float* W = (mat == 0) ? Wq : (mat == 1) ? Wk : Wv;
    float acc = 0.f;
    #pragma unroll
    for (int j = 0; j < HDIM; j++) acc += a[j] * W[j * HDIM + c];
    // fold bias into the feature-0 rows (every node uses exactly one of them)
    if (r < 119) acc += ((mat == 0) ? bq : (mat == 1) ? bk : bv)[c];
    int p = ((c & 7) << 3) + (c >> 3);       // head-major position
    if (mat == 0)      g_embQ[r * HDIM + p] = acc * QK_SCALE;
    else if (mat == 1) g_embK[r * HDIM + p] = acc;
    else               g_embV[r * HDIM + p] = acc;
}

// ---------------- K_gather_scatter: node QKV gather  ||  edge adjacency -----
__global__ void k_gather_scatter(const int* __restrict__ X,
                                 const int* __restrict__ row,
                                 const int* __restrict__ col) {
    int b = blockIdx.x, t = threadIdx.x;
    if (b >= QKV_NB) {                       // adjacency half of the grid
        int e = (b - QKV_NB) * 256 + t;
        if (e < N_EDGES) {
            int r = row[e];
            int pos = atomicAdd(&g_cnt[r], 1);
            if (pos < MAXDEG) g_scol[(size_t)r * MAXDEG + pos] = col[e];
        }
        return;
    }
    int tid = b * 256 + t;
    int n = tid >> 4, t16 = tid & 15;        // 16 threads/node, float4 each

    const float4* eq = (const float4*)g_embQ;
    const float4* ek = (const float4*)g_embK;
    const float4* ev = (const float4*)g_embV;

    float4 aq = make_float4(0.f, 0.f, 0.f, 0.f);
    float4 ak = aq, av = aq;
    #pragma unroll
    for (int f = 0; f < NFEAT; f++) {
        int idx = X[n * NFEAT + f] + c_offs[f];
        int base = idx * 16 + t16;
        float4 q = eq[base]; aq.x += q.x; aq.y += q.y; aq.z += q.z; aq.w += q.w;
        float4 k = ek[base]; ak.x += k.x; ak.y += k.y; ak.z += k.z; ak.w += k.w;
        float4 v = ev[base]; av.x += v.x; av.y += v.y; av.z += v.z; av.w += v.w;
    }
    ((float4*)g_Q)[n * 16 + t16] = aq;
    ((float4*)g_K)[n * 16 + t16] = ak;
    __half2 v01 = __floats2half2_rn(av.x, av.y);
    __half2 v23 = __floats2half2_rn(av.z, av.w);
    uint2 o;
    o.x = *(unsigned*)&v01; o.y = *(unsigned*)&v23;
    *(uint2*)(g_Vh + n * HDIM + 4 * t16) = o;
}

// ---------------- K_fused: SDDMM + softmax + SpMM (16 lanes/edge) -----------
// Adjacency row held in ONE register per warp (lane i holds scol[i], covers
// the first 32 edges; LDG fallback beyond). Column index via SHFL.IDX so the
// K/V gathers have no dependent-load prefix. exp(s) fp32-safe; exp/sum ==
// softmax exactly.
__global__ __launch_bounds__(256) void k_fused() {
    int g = blockIdx.x * blockDim.x + threadIdx.x;
    int n = g >> 5;
    if (n >= N_NODES) return;
    int lane = threadIdx.x & 31;
    int slot = lane >> 4, t = lane & 15;
    size_t base = (size_t)n * MAXDEG;
    int len = min(g_cnt[n], MAXDEG);

    int c_reg = g_scol[base + lane];         // edges 0..31 (zero-init tail safe)
    float4 q = ((const float4*)(g_Q + n * HDIM))[t];

    float sum = 0.f;
    float4 acc = make_float4(0.f, 0.f, 0.f, 0.f);
    #pragma unroll 4
    for (int i = 0; i < len; i += 2) {
        int idx = i + slot;
        bool valid = idx < len;
        int c;
        if (i + 1 < 32) c = __shfl_sync(0xffffffffu, c_reg, idx);
        else            c = g_scol[base + (valid ? idx : i)];
        float4 k = ((const float4*)(g_K + c * HDIM))[t];
        uint2 vraw = *(const uint2*)(g_Vh + c * HDIM + 4 * t);
        float2 v01 = __half22float2(*(__half2*)&vraw.x);
        float2 v23 = __half22float2(*(__half2*)&vraw.y);
        float s = q.x * k.x + q.y * k.y + q.z * k.z + q.w * k.w;
        s += __shfl_xor_sync(0xffffffffu, s, 1);   // pair -> full head dot
        float p = valid ? __expf(s) : 0.f;
        sum += p;
        acc.x += p * v01.x; acc.y += p * v01.y;
        acc.z += p * v23.x; acc.w += p * v23.y;
    }
    sum   += __shfl_xor_sync(0xffffffffu, sum,   16);
    acc.x += __shfl_xor_sync(0xffffffffu, acc.x, 16);
    acc.y += __shfl_xor_sync(0xffffffffu, acc.y, 16);
    acc.z += __shfl_xor_sync(0xffffffffu, acc.z, 16);
    acc.w += __shfl_xor_sync(0xffffffffu, acc.w, 16);
    float inv = (len > 0) ? (1.0f / sum) : 0.f;
    if (lane < 16) {
        __half2 o01 = __floats2half2_rn(acc.x * inv, acc.y * inv);
        __half2 o23 = __floats2half2_rn(acc.z * inv, acc.w * inv);
        uint2 o;
        o.x = *(unsigned*)&o01; o.y = *(unsigned*)&o23;
        *(uint2*)(g_AVh + n * HDIM + 4 * t) = o;
    }
}

// ---------------- K_out: tensor-core GEMM  out = AV @ Wo + bo ---------------
// Block = 256 threads (8 warps), 128 nodes/block. Wo staged from the
// pre-permuted fp16 copy (8 KB, no index math); AV tile staged as half2.
// Each warp: 16 nodes x 64 cols via mma.sync.m16n8k16 (8 n-tiles x 4 k).
__global__ __launch_bounds__(256) void k_out(const float* __restrict__ bo,
                                             float* __restrict__ out) {
    __shared__ __half Ws[HDIM][72];          // [k_p][c]
    __shared__ __half As[128][72];           // [node][k_p]
    __shared__ float  bos[HDIM];

    int t = threadIdx.x;
    size_t nb = (size_t)blockIdx.x * 128;

    // stage pre-permuted fp16 Wo (coalesced half2)
    #pragma unroll
    for (int j = 0; j < 8; j++) {
        int idx = t + 256 * j;               // 2048 half2
        int d = idx >> 5, k2 = idx & 31;
        *(__half2*)&Ws[d][2 * k2] = ((const __half2*)g_Woh)[idx];
    }
    if (t < HDIM) bos[t] = bo[t];

    // stage AV tile (coalesced half2)
    #pragma unroll
    for (int j = 0; j < 16; j++) {
        int idx = t + 256 * j;               // 4096 half2
        int r = idx >> 5, k2 = idx & 31;
        __half2 h = (nb + r < N_NODES)
                  ? ((const __half2*)g_AVh)[(nb + r) * 32 + k2]
                  : __float2half2_rn(0.f);
        *(__half2*)&As[r][2 * k2] = h;
    }
    __syncthreads();

    int w = t >> 5, l = t & 31;

    // A fragments: 4 k-steps of m16k16
    unsigned a[4][4];
    #pragma unroll
    for (int kk = 0; kk < 4; kk++) {
        unsigned addr = (unsigned)__cvta_generic_to_shared(
            &As[w * 16 + (l & 15)][kk * 16 + (l >> 4) * 8]);
        asm volatile("ldmatrix.sync.aligned.m8n8.x4.shared.b16 {%0,%1,%2,%3}, [%4];"
                     : "=r"(a[kk][0]), "=r"(a[kk][1]), "=r"(a[kk][2]), "=r"(a[kk][3])
                     : "r"(addr));
    }

    int g0 = l >> 2;                         // C-fragment row group
    int c0 = (l & 3) * 2;
    #pragma unroll
    for (int nt = 0; nt < 8; nt++) {
        float d0 = 0.f, d1 = 0.f, d2 = 0.f, d3 = 0.f;
        #pragma unroll
        for (int kk = 0; kk < 4; kk++) {
            unsigned b0, b1;
            unsigned baddr = (unsigned)__cvta_generic_to_shared(
                &Ws[kk * 16 + (l & 15)][nt * 8]);
            asm volatile("ldmatrix.sync.aligned.m8n8.x2.trans.shared.b16 {%0,%1}, [%2];"
                         : "=r"(b0), "=r"(b1) : "r"(baddr));
            asm volatile(
                "mma.sync.aligned.m16n8k16.row.col.f32.f16.f16.f32 "
                "{%0,%1,%2,%3},{%4,%5,%6,%7},{%8,%9},{%0,%1,%2,%3};"
                : "+f"(d0), "+f"(d1), "+f"(d2), "+f"(d3)
                : "r"(a[kk][0]), "r"(a[kk][1]), "r"(a[kk][2]), "r"(a[kk][3]),
                  "r"(b0), "r"(b1));
        }
        int cc = nt * 8 + c0;
        float bx = bos[cc], by = bos[cc + 1];
        size_t n0 = nb + w * 16 + g0;
        if (n0 < N_NODES)
            *(float2*)&out[n0 * HDIM + cc] = make_float2(d0 + bx, d1 + by);
        if (n0 + 8 < N_NODES)
            *(float2*)&out[(n0 + 8) * HDIM + cc] = make_float2(d2 + bx, d3 + by);
    }
}

// ---------------- launch -----------------------------------------------------
extern "C" void kernel_launch(void* const* d_in, const int* in_sizes, int n_in,
                              void* d_out, int out_size) {
    const int*   X        = (const int*)  d_in[0];
    const int*   row      = (const int*)  d_in[1];
    const int*   col      = (const int*)  d_in[2];
    const float* atom_emb = (const float*)d_in[3];
    const float* Wq       = (const float*)d_in[4];
    const float* bq       = (const float*)d_in[5];
    const float* Wk       = (const float*)d_in[6];
    const float* bk       = (const float*)d_in[7];
    const float* Wv       = (const float*)d_in[8];
    const float* bv       = (const float*)d_in[9];
    const float* Wo       = (const float*)d_in[10];
    const float* bo       = (const float*)d_in[11];
    float* out = (float*)d_out;

    (void)in_sizes; (void)n_in; (void)out_size;

    k_prep<<<ZERO_NB + WO_NB + N_EMB, 256>>>(atom_emb, Wq, bq, Wk, bk, Wv, bv, Wo);
    k_gather_scatter<<<QKV_NB + EDGE_NB, 256>>>(X, row, col);
    k_fused<<<(N_NODES * 32 + 255) / 256, 256>>>();
    k_out<<<OUT_NB, 256>>>(bo, out);
}